// round 6
// baseline (speedup 1.0000x reference)
#include <cuda_runtime.h>

// Problem dims (fixed by the dataset)
#define NN0   200000
#define NN1   100000
#define NN2   20000
#define NE1   1600000
#define NE2   320000
#define DIN   128
#define DH    256
#define DOUT  64

// ---------------------------------------------------------------------------
// Scratch (static __device__ globals — no allocation allowed)
// ---------------------------------------------------------------------------
__device__ float g_agg1[(size_t)NN1 * DIN];   // 51.2 MB
__device__ float g_cnt1[NN1];
__device__ float g_inv1[NN1];
__device__ float g_h1[(size_t)NN1 * DH];      // 102.4 MB
__device__ float g_agg2[(size_t)NN2 * DH];    // 20.5 MB
__device__ float g_cnt2[NN2];
__device__ float g_inv2[NN2];

// ---------------------------------------------------------------------------
// 0) zero the accumulators (must happen every replay — graph is re-run)
// ---------------------------------------------------------------------------
__global__ void k_init() {
    int i = blockIdx.x * blockDim.x + threadIdx.x;
    int stride = gridDim.x * blockDim.x;
    float4 z = make_float4(0.f, 0.f, 0.f, 0.f);
    for (int j = i; j < (NN1 * DIN) / 4; j += stride) ((float4*)g_agg1)[j] = z;
    for (int j = i; j < (NN2 * DH) / 4; j += stride) ((float4*)g_agg2)[j] = z;
    for (int j = i; j < NN1; j += stride) g_cnt1[j] = 0.f;
    for (int j = i; j < NN2; j += stride) g_cnt2[j] = 0.f;
}

// ---------------------------------------------------------------------------
// vector global reduction: red.global.add.v4.f32 (sm_90+)
// ---------------------------------------------------------------------------
__device__ __forceinline__ void red_add_v4(float* p, float4 v) {
    asm volatile("red.global.add.v4.f32 [%0], {%1,%2,%3,%4};"
                 :: "l"(p), "f"(v.x), "f"(v.y), "f"(v.z), "f"(v.w)
                 : "memory");
}

// ---------------------------------------------------------------------------
// 1) scatter-add layer 1: one warp per edge, 32 lanes x float4 = 128 floats
// ---------------------------------------------------------------------------
__global__ __launch_bounds__(256) void k_scatter1(const float* __restrict__ x,
                                                  const int* __restrict__ src,
                                                  const int* __restrict__ dst) {
    int warp = (blockIdx.x * blockDim.x + threadIdx.x) >> 5;
    int lane = threadIdx.x & 31;
    if (warp >= NE1) return;
    int s = __ldg(src + warp);
    int d = __ldg(dst + warp);
    const float4* xr = (const float4*)(x + (size_t)s * DIN);
    float4 v = __ldg(xr + lane);
    red_add_v4(g_agg1 + (size_t)d * DIN + lane * 4, v);
    if (lane == 0) atomicAdd(g_cnt1 + d, 1.0f);
}

__global__ void k_inv1() {
    int i = blockIdx.x * blockDim.x + threadIdx.x;
    if (i < NN1) g_inv1[i] = 1.0f / fmaxf(g_cnt1[i], 1.0f);
}

// ---------------------------------------------------------------------------
// 2) GEMM1 fused: h1 = relu( (agg1*inv1) @ W_l1^T + x @ W_r1^T + b_l1 )
//    Single NT GEMM with virtual K=256 (k<128: agg1/W_l1, k>=128: x/W_r1).
//    BM=128, BN=128, BK=16, 256 threads, 8x8 microtile. Double-buffered smem,
//    one __syncthreads per k-tile. (256,2) pins 2 CTAs/SM (reg cap 128).
// ---------------------------------------------------------------------------
__global__ __launch_bounds__(256, 2) void k_gemm1(const float* __restrict__ x,
                                                  const float* __restrict__ Wl,
                                                  const float* __restrict__ Wr,
                                                  const float* __restrict__ bias) {
    __shared__ float As[2][16][132];   // [buf][k][m], padded
    __shared__ float Bs[2][16][128];   // [buf][k][n]

    const int m0 = blockIdx.y * 128;
    const int n0 = blockIdx.x * 128;
    const int tid = threadIdx.x;
    const int tx = tid & 15;        // 0..15 -> n group
    const int ty = tid >> 4;        // 0..15 -> m group
    const int arow = tid >> 2;      // 0..63
    const int acol = (tid & 3) * 4; // 0,4,8,12

    int mrow[2];
    float sc[2];
    bool mok[2];
#pragma unroll
    for (int r = 0; r < 2; ++r) {
        mrow[r] = m0 + arow + r * 64;
        mok[r] = (mrow[r] < NN1);
        sc[r] = mok[r] ? g_inv1[mrow[r]] : 0.f;
    }

    float acc[8][8];
#pragma unroll
    for (int i = 0; i < 8; ++i)
#pragma unroll
        for (int j = 0; j < 8; ++j) acc[i][j] = 0.f;

    float4 ra[2], rb[2];

    auto load_tile = [&](int kt) {
        const int kbase = kt * 16;
        const bool first = (kbase < DIN);
        const int kk = first ? kbase : (kbase - DIN);
#pragma unroll
        for (int r = 0; r < 2; ++r) {
            float4 v = make_float4(0.f, 0.f, 0.f, 0.f);
            if (mok[r]) {
                if (first) {
                    v = *(const float4*)(g_agg1 + (size_t)mrow[r] * DIN + kk + acol);
                    v.x *= sc[r]; v.y *= sc[r]; v.z *= sc[r]; v.w *= sc[r];
                } else {
                    v = __ldg((const float4*)(x + (size_t)mrow[r] * DIN + kk + acol));
                }
            }
            ra[r] = v;
        }
        const float* W = first ? Wl : Wr;
#pragma unroll
        for (int r = 0; r < 2; ++r) {
            int n = n0 + arow + r * 64;
            rb[r] = __ldg((const float4*)(W + (size_t)n * DIN + kk + acol));
        }
    };
    auto store_tile = [&](int buf) {
#pragma unroll
        for (int r = 0; r < 2; ++r) {
            As[buf][acol + 0][arow + r * 64] = ra[r].x;
            As[buf][acol + 1][arow + r * 64] = ra[r].y;
            As[buf][acol + 2][arow + r * 64] = ra[r].z;
            As[buf][acol + 3][arow + r * 64] = ra[r].w;
            Bs[buf][acol + 0][arow + r * 64] = rb[r].x;
            Bs[buf][acol + 1][arow + r * 64] = rb[r].y;
            Bs[buf][acol + 2][arow + r * 64] = rb[r].z;
            Bs[buf][acol + 3][arow + r * 64] = rb[r].w;
        }
    };

    load_tile(0);
    store_tile(0);
    __syncthreads();

    for (int kt = 0; kt < 16; ++kt) {
        const int buf = kt & 1;
        if (kt < 15) load_tile(kt + 1);   // gmem loads in flight during compute

#pragma unroll
        for (int k = 0; k < 16; ++k) {
            float a[8], b[8];
            *(float4*)(a)     = *(const float4*)&As[buf][k][ty * 8];
            *(float4*)(a + 4) = *(const float4*)&As[buf][k][ty * 8 + 4];
            *(float4*)(b)     = *(const float4*)&Bs[buf][k][tx * 8];
            *(float4*)(b + 4) = *(const float4*)&Bs[buf][k][tx * 8 + 4];
#pragma unroll
            for (int i = 0; i < 8; ++i)
#pragma unroll
                for (int j = 0; j < 8; ++j)
                    acc[i][j] += a[i] * b[j];
        }

        if (kt < 15) {
            store_tile(buf ^ 1);          // other buffer: no hazard with readers
            __syncthreads();              // publish before next iteration reads
        }
    }

    // epilogue: bias + relu -> g_h1, vectorized float4 stores
    float bv[8];
#pragma unroll
    for (int j = 0; j < 8; ++j) bv[j] = __ldg(bias + n0 + tx * 8 + j);
#pragma unroll
    for (int i = 0; i < 8; ++i) {
        int m = m0 + ty * 8 + i;
        if (m >= NN1) continue;
        float* op = g_h1 + (size_t)m * DH + n0 + tx * 8;
#pragma unroll
        for (int j = 0; j < 8; j += 4) {
            float4 o;
            o.x = fmaxf(acc[i][j + 0] + bv[j + 0], 0.f);
            o.y = fmaxf(acc[i][j + 1] + bv[j + 1], 0.f);
            o.z = fmaxf(acc[i][j + 2] + bv[j + 2], 0.f);
            o.w = fmaxf(acc[i][j + 3] + bv[j + 3], 0.f);
            *(float4*)(op + j) = o;
        }
    }
}

// ---------------------------------------------------------------------------
// 3) scatter-add layer 2: warp per edge, 256 floats = 2 float4 per lane
// ---------------------------------------------------------------------------
__global__ __launch_bounds__(256) void k_scatter2(const int* __restrict__ src,
                                                  const int* __restrict__ dst) {
    int warp = (blockIdx.x * blockDim.x + threadIdx.x) >> 5;
    int lane = threadIdx.x & 31;
    if (warp >= NE2) return;
    int s = __ldg(src + warp);
    int d = __ldg(dst + warp);
    const float4* hr = (const float4*)(g_h1 + (size_t)s * DH);
    float4 v0 = hr[lane];
    float4 v1 = hr[lane + 32];
    float* base = g_agg2 + (size_t)d * DH;
    red_add_v4(base + lane * 4, v0);
    red_add_v4(base + (lane + 32) * 4, v1);
    if (lane == 0) atomicAdd(g_cnt2 + d, 1.0f);
}

__global__ void k_inv2() {
    int i = blockIdx.x * blockDim.x + threadIdx.x;
    if (i < NN2) g_inv2[i] = 1.0f / fmaxf(g_cnt2[i], 1.0f);
}

// ---------------------------------------------------------------------------
// 4) GEMM2 + fused log_softmax:
//    h2 = (agg2*inv2) @ W_l2^T + h1[:N2] @ W_r2^T + b_l2 ; out = lsm(h2)
//    virtual K = 512. BM=64, BN=64(=DOUT: full rows in-CTA), 4x4 microtile.
//    Double-buffered; epilogue does row-wise max/sum-exp via smem reduction
//    and writes log-probabilities straight to d_out (g_h2 eliminated).
//    (256,4): ~47 regs/thread fits 64-reg cap; higher residency for the tail.
// ---------------------------------------------------------------------------
__global__ __launch_bounds__(256, 4) void k_gemm2(const float* __restrict__ Wl,
                                                  const float* __restrict__ Wr,
                                                  const float* __restrict__ bias,
                                                  float* __restrict__ out) {
    __shared__ float As[2][16][68];
    __shared__ float Bs[2][16][64];

    const int m0 = blockIdx.x * 64;
    const int tid = threadIdx.x;
    const int tx = tid & 15;
    const int ty = tid >> 4;
    const int arow = tid >> 2;      // 0..63
    const int acol = (tid & 3) * 4; // 0,4,8,12

    float acc[4][4];
#pragma unroll
    for (int i = 0; i < 4; ++i)
#pragma unroll
        for (int j = 0; j < 4; ++j) acc[i][j] = 0.f;

    const int m = m0 + arow;
    const bool mok = (m < NN2);
    const float sc = mok ? g_inv2[m] : 0.f;

    float4 ra, rb;
    auto load_tile = [&](int kt) {
        const int kbase = kt * 16;
        const bool first = (kbase < DH);
        const int kk = first ? kbase : (kbase - DH);
        float4 v = make_float4(0.f, 0.f, 0.f, 0.f);
        if (mok) {
            if (first) {
                v = *(const float4*)(g_agg2 + (size_t)m * DH + kk + acol);
                v.x *= sc; v.y *= sc; v.z *= sc; v.w *= sc;
            } else {
                v = *(const float4*)(g_h1 + (size_t)m * DH + kk + acol);
            }
        }
        ra = v;
        const float* W = first ? Wl : Wr;
        rb = __ldg((const float4*)(W + (size_t)arow * DH + kk + acol));
    };
    auto store_tile = [&](int buf) {
        As[buf][acol + 0][arow] = ra.x;
        As[buf][acol + 1][arow] = ra.y;
        As[buf][acol + 2][arow] = ra.z;
        As[buf][acol + 3][arow] = ra.w;
        Bs[buf][acol + 0][arow] = rb.x;
        Bs[buf][acol + 1][arow] = rb.y;
        Bs[buf][acol + 2][arow] = rb.z;
        Bs[buf][acol + 3][arow] = rb.w;
    };

    load_tile(0);
    store_tile(0);
    __syncthreads();

    for (int kt = 0; kt < 32; ++kt) {
        const int buf = kt & 1;
        if (kt < 31) load_tile(kt + 1);

#pragma unroll
        for (int k = 0; k < 16; ++k) {
            float a[4], b[4];
            *(float4*)a = *(const float4*)&As[buf][k][ty * 4];
            *(float4*)b = *(const float4*)&Bs[buf][k][tx * 4];
#pragma unroll
            for (int i = 0; i < 4; ++i)
#pragma unroll
                for (int j = 0; j < 4; ++j)
                    acc[i][j] += a[i] * b[j];
        }

        if (kt < 31) {
            store_tile(buf ^ 1);
            __syncthreads();
        }
    }

    // ---- epilogue: bias, then fused log_softmax over the 64 columns ----
    float bv[4];
#pragma unroll
    for (int j = 0; j < 4; ++j) bv[j] = __ldg(bias + tx * 4 + j);

    float vout[4][4];
#pragma unroll
    for (int i = 0; i < 4; ++i)
#pragma unroll
        for (int j = 0; j < 4; ++j) vout[i][j] = acc[i][j] + bv[j];

    __syncthreads();                       // done with As/Bs; reuse as scratch
    float* red = (float*)As;               // needs 64*17 = 1088 floats (< 2176)

    // pass 1: row max (16 tx threads per row, 4 cols each)
    float mx[4];
#pragma unroll
    for (int i = 0; i < 4; ++i) {
        float v = fmaxf(fmaxf(vout[i][0], vout[i][1]),
                        fmaxf(vout[i][2], vout[i][3]));
        red[(ty * 4 + i) * 17 + tx] = v;
    }
    __syncthreads();
#pragma unroll
    for (int i = 0; i < 4; ++i) {
        float v = -3.402823466e38f;
        const float* rr = red + (ty * 4 + i) * 17;
#pragma unroll
        for (int t = 0; t < 16; ++t) v = fmaxf(v, rr[t]);
        mx[i] = v;
    }
    __syncthreads();

    // pass 2: row sum of exp
    float lse[4];
#pragma unroll
    for (int i = 0; i < 4; ++i) {
        float s = __expf(vout[i][0] - mx[i]) + __expf(vout[i][1] - mx[i])
                + __expf(vout[i][2] - mx[i]) + __expf(vout[i][3] - mx[i]);
        red[(ty * 4 + i) * 17 + tx] = s;
    }
    __syncthreads();
#pragma unroll
    for (int i = 0; i < 4; ++i) {
        float s = 0.f;
        const float* rr = red + (ty * 4 + i) * 17;
#pragma unroll
        for (int t = 0; t < 16; ++t) s += rr[t];
        lse[i] = mx[i] + logf(s);
    }

    // write log-probabilities
#pragma unroll
    for (int i = 0; i < 4; ++i) {
        int mm = m0 + ty * 4 + i;
        if (mm >= NN2) continue;
        float4 o;
        o.x = vout[i][0] - lse[i];
        o.y = vout[i][1] - lse[i];
        o.z = vout[i][2] - lse[i];
        o.w = vout[i][3] - lse[i];
        *(float4*)(out + (size_t)mm * DOUT + tx * 4) = o;
    }
}

// ---------------------------------------------------------------------------
// launch
// ---------------------------------------------------------------------------
extern "C" void kernel_launch(void* const* d_in, const int* in_sizes, int n_in,
                              void* d_out, int out_size) {
    const float* x    = (const float*)d_in[0];
    const int*   src1 = (const int*)d_in[1];
    const int*   dst1 = (const int*)d_in[2];
    const int*   src2 = (const int*)d_in[3];
    const int*   dst2 = (const int*)d_in[4];
    const float* Wl1  = (const float*)d_in[5];
    const float* bl1  = (const float*)d_in[6];
    const float* Wr1  = (const float*)d_in[7];
    const float* Wl2  = (const float*)d_in[8];
    const float* bl2  = (const float*)d_in[9];
    const float* Wr2  = (const float*)d_in[10];
    float* out = (float*)d_out;

    k_init<<<4096, 256>>>();
    k_scatter1<<<NE1 / 8, 256>>>(x, src1, dst1);          // 1 warp/edge
    k_inv1<<<(NN1 + 255) / 256, 256>>>();
    k_gemm1<<<dim3(2, (NN1 + 127) / 128), 256>>>(x, Wl1, Wr1, bl1);
    k_scatter2<<<NE2 / 8, 256>>>(src2, dst2);
    k_inv2<<<(NN2 + 255) / 256, 256>>>();
    k_gemm2<<<(NN2 + 63) / 64, 256>>>(Wl2, Wr2, bl2, out);
}

// round 7
// speedup vs baseline: 1.2679x; 1.2679x over previous
#include <cuda_runtime.h>
#include <cstdint>

// Problem dims (fixed by the dataset)
#define NN0   200000
#define NN1   100000
#define NN2   20000
#define NE1   1600000
#define NE2   320000
#define DIN   128
#define DH    256
#define DOUT  64

// GEMM1 tiling
#define BM1   64
#define BN1   256          // = DH: single n-block, A read once
#define BK1   32
#define ASTR  72           // As [k][m] stride: 72 % 32 == 8  -> conflict-free frags
#define BSTR  36           // Bs [n][k] stride: 36 % 32 == 4  -> conflict-free frags
#define SMEM1_BYTES ((2 * BK1 * ASTR + 2 * BN1 * BSTR) * 4)   // 92160 B

// ---------------------------------------------------------------------------
// Scratch (static __device__ globals — no allocation allowed)
// ---------------------------------------------------------------------------
__device__ float g_agg1[(size_t)NN1 * DIN];   // 51.2 MB
__device__ float g_cnt1[NN1];
__device__ float g_inv1[NN1];
__device__ float g_h1[(size_t)NN1 * DH];      // 102.4 MB
__device__ float g_agg2[(size_t)NN2 * DH];    // 20.5 MB
__device__ float g_cnt2[NN2];
__device__ float g_inv2[NN2];

// ---------------------------------------------------------------------------
// 0) zero the accumulators (must happen every replay — graph is re-run)
// ---------------------------------------------------------------------------
__global__ void k_init() {
    int i = blockIdx.x * blockDim.x + threadIdx.x;
    int stride = gridDim.x * blockDim.x;
    float4 z = make_float4(0.f, 0.f, 0.f, 0.f);
    for (int j = i; j < (NN1 * DIN) / 4; j += stride) ((float4*)g_agg1)[j] = z;
    for (int j = i; j < (NN2 * DH) / 4; j += stride) ((float4*)g_agg2)[j] = z;
    for (int j = i; j < NN1; j += stride) g_cnt1[j] = 0.f;
    for (int j = i; j < NN2; j += stride) g_cnt2[j] = 0.f;
}

// ---------------------------------------------------------------------------
// helpers
// ---------------------------------------------------------------------------
__device__ __forceinline__ void red_add_v4(float* p, float4 v) {
    asm volatile("red.global.add.v4.f32 [%0], {%1,%2,%3,%4};"
                 :: "l"(p), "f"(v.x), "f"(v.y), "f"(v.z), "f"(v.w)
                 : "memory");
}

__device__ __forceinline__ float to_tf32(float f) {
    uint32_t u;
    asm("cvt.rna.tf32.f32 %0, %1;" : "=r"(u) : "f"(f));
    return __uint_as_float(u);
}

__device__ __forceinline__ void mma_tf32(float* c, const uint32_t* a,
                                         uint32_t b0, uint32_t b1) {
    asm volatile(
        "mma.sync.aligned.m16n8k8.row.col.f32.tf32.tf32.f32 "
        "{%0,%1,%2,%3}, {%4,%5,%6,%7}, {%8,%9}, {%0,%1,%2,%3};"
        : "+f"(c[0]), "+f"(c[1]), "+f"(c[2]), "+f"(c[3])
        : "r"(a[0]), "r"(a[1]), "r"(a[2]), "r"(a[3]), "r"(b0), "r"(b1));
}

__device__ __forceinline__ void cp_async16(void* smem_dst, const void* gmem_src) {
    uint32_t d = (uint32_t)__cvta_generic_to_shared(smem_dst);
    asm volatile("cp.async.ca.shared.global [%0], [%1], 16;"
                 :: "r"(d), "l"(gmem_src) : "memory");
}

// ---------------------------------------------------------------------------
// 1) scatter-add layer 1: one warp per edge, 32 lanes x float4 = 128 floats
// ---------------------------------------------------------------------------
__global__ __launch_bounds__(256) void k_scatter1(const float* __restrict__ x,
                                                  const int* __restrict__ src,
                                                  const int* __restrict__ dst) {
    int warp = (blockIdx.x * blockDim.x + threadIdx.x) >> 5;
    int lane = threadIdx.x & 31;
    if (warp >= NE1) return;
    int s = __ldg(src + warp);
    int d = __ldg(dst + warp);
    const float4* xr = (const float4*)(x + (size_t)s * DIN);
    float4 v = __ldg(xr + lane);
    red_add_v4(g_agg1 + (size_t)d * DIN + lane * 4, v);
    if (lane == 0) atomicAdd(g_cnt1 + d, 1.0f);
}

__global__ void k_inv1() {
    int i = blockIdx.x * blockDim.x + threadIdx.x;
    if (i < NN1) g_inv1[i] = 1.0f / fmaxf(g_cnt1[i], 1.0f);
}

// ---------------------------------------------------------------------------
// 2) GEMM1 (tf32 tensor core):
//    h1 = relu( (agg1*inv1) @ W_l1^T + x @ W_r1^T + b_l1 )
//    Virtual K=256 (kt<4: agg1/W_l1, kt>=4: x/W_r1). BM=64, BN=256, BK=32.
//    8 warps (2m x 4n), warp tile 32x64 of m16n8k8 tf32 MMAs.
//    B: cp.async gmem->smem (raw fp32, HW-truncated tf32).
//    A: register-staged (inv1 scale on first half) + cvt.rna.tf32.
// ---------------------------------------------------------------------------
__global__ __launch_bounds__(256, 2) void k_gemm1(const float* __restrict__ x,
                                                  const float* __restrict__ Wl,
                                                  const float* __restrict__ Wr,
                                                  const float* __restrict__ bias) {
    extern __shared__ float smem[];
    float* Asm = smem;                       // 2 * BK1 * ASTR
    float* Bsm = smem + 2 * BK1 * ASTR;      // 2 * BN1 * BSTR

    const int tid  = threadIdx.x;
    const int warp = tid >> 5;
    const int lane = tid & 31;
    const int l4   = lane >> 2;              // 0..7
    const int la3  = lane & 3;               // 0..3
    const int wm   = (warp & 1) * 32;        // 2 warps in m
    const int wn   = (warp >> 1) * 64;       // 4 warps in n
    const int m0   = blockIdx.x * BM1;

    // A loader mapping: row = tid & 63, cols acg..acg+7
    const int arow = tid & 63;
    const int acg  = (tid >> 6) * 8;
    const int am   = m0 + arow;
    const bool amok = (am < NN1);
    const float ascale = amok ? g_inv1[am] : 0.f;

    float acc[2][8][4];
#pragma unroll
    for (int mt = 0; mt < 2; ++mt)
#pragma unroll
        for (int nt = 0; nt < 8; ++nt)
#pragma unroll
            for (int q = 0; q < 4; ++q) acc[mt][nt][q] = 0.f;

    // ---- B tile: cp.async, n = tid (one row per thread), 8 x 16B ----
    auto cp_b = [&](int kt, int buf) {
        const float* W = (kt < 4) ? Wl : Wr;
        const int kk = (kt * BK1) & (DIN - 1);
        const float* src = W + (size_t)tid * DIN + kk;
        float* dst = Bsm + buf * (BN1 * BSTR) + tid * BSTR;
#pragma unroll
        for (int c = 0; c < BK1; c += 4)
            cp_async16(dst + c, src + c);
        asm volatile("cp.async.commit_group;" ::: "memory");
    };

    // ---- A tile: gmem -> regs (scale on agg1 half) ----
    auto load_a = [&](int kt, float4& v0, float4& v1) {
        v0 = make_float4(0.f, 0.f, 0.f, 0.f);
        v1 = v0;
        if (!amok) return;
        if (kt < 4) {
            const float* p = g_agg1 + (size_t)am * DIN + kt * BK1 + acg;
            v0 = *(const float4*)p;
            v1 = *(const float4*)(p + 4);
            v0.x *= ascale; v0.y *= ascale; v0.z *= ascale; v0.w *= ascale;
            v1.x *= ascale; v1.y *= ascale; v1.z *= ascale; v1.w *= ascale;
        } else {
            const float* p = x + (size_t)am * DIN + (kt * BK1 - DIN) + acg;
            v0 = __ldg((const float4*)p);
            v1 = __ldg((const float4*)(p + 4));
        }
    };
    // ---- regs -> As[k][m] with tf32 rounding ----
    auto sts_a = [&](int buf, float4 v0, float4 v1) {
        float* dst = Asm + buf * (BK1 * ASTR);
        dst[(acg + 0) * ASTR + arow] = to_tf32(v0.x);
        dst[(acg + 1) * ASTR + arow] = to_tf32(v0.y);
        dst[(acg + 2) * ASTR + arow] = to_tf32(v0.z);
        dst[(acg + 3) * ASTR + arow] = to_tf32(v0.w);
        dst[(acg + 4) * ASTR + arow] = to_tf32(v1.x);
        dst[(acg + 5) * ASTR + arow] = to_tf32(v1.y);
        dst[(acg + 6) * ASTR + arow] = to_tf32(v1.z);
        dst[(acg + 7) * ASTR + arow] = to_tf32(v1.w);
    };

    // prologue: tile 0
    cp_b(0, 0);
    {
        float4 a0, a1;
        load_a(0, a0, a1);
        sts_a(0, a0, a1);
    }
    asm volatile("cp.async.wait_group 0;" ::: "memory");
    __syncthreads();

    for (int kt = 0; kt < 8; ++kt) {
        const int buf = kt & 1;
        float4 na0, na1;
        if (kt < 7) {
            cp_b(kt + 1, buf ^ 1);          // async, in flight during MMAs
            load_a(kt + 1, na0, na1);       // LDGs issued, consumed after MMAs
        }

        const float* Ab = Asm + buf * (BK1 * ASTR);
        const float* Bb = Bsm + buf * (BN1 * BSTR);
#pragma unroll
        for (int k8 = 0; k8 < BK1; k8 += 8) {
            uint32_t af[2][4];
#pragma unroll
            for (int mt = 0; mt < 2; ++mt) {
                const int r = wm + mt * 16 + l4;
                const int c = k8 + la3;
                af[mt][0] = __float_as_uint(Ab[c * ASTR + r]);
                af[mt][1] = __float_as_uint(Ab[c * ASTR + r + 8]);
                af[mt][2] = __float_as_uint(Ab[(c + 4) * ASTR + r]);
                af[mt][3] = __float_as_uint(Ab[(c + 4) * ASTR + r + 8]);
            }
#pragma unroll
            for (int nt = 0; nt < 8; ++nt) {
                const int n = wn + nt * 8 + l4;
                uint32_t b0 = __float_as_uint(Bb[n * BSTR + k8 + la3]);
                uint32_t b1 = __float_as_uint(Bb[n * BSTR + k8 + 4 + la3]);
                mma_tf32(acc[0][nt], af[0], b0, b1);
                mma_tf32(acc[1][nt], af[1], b0, b1);
            }
        }

        if (kt < 7) {
            sts_a(buf ^ 1, na0, na1);       // other buffer: no hazard
            asm volatile("cp.async.wait_group 0;" ::: "memory");
            __syncthreads();
        }
    }

    // ---- epilogue: bias + relu -> g_h1 (float2 stores, mma C layout) ----
#pragma unroll
    for (int mt = 0; mt < 2; ++mt) {
        const int r0 = m0 + wm + mt * 16 + l4;
#pragma unroll
        for (int half = 0; half < 2; ++half) {
            const int m = r0 + half * 8;
            if (m >= NN1) continue;
            float* rowp = g_h1 + (size_t)m * DH;
#pragma unroll
            for (int nt = 0; nt < 8; ++nt) {
                const int ncol = wn + nt * 8 + 2 * la3;
                float2 o;
                o.x = fmaxf(acc[mt][nt][half * 2 + 0] + __ldg(bias + ncol), 0.f);
                o.y = fmaxf(acc[mt][nt][half * 2 + 1] + __ldg(bias + ncol + 1), 0.f);
                *(float2*)(rowp + ncol) = o;
            }
        }
    }
}

// ---------------------------------------------------------------------------
// 3) scatter-add layer 2: warp per edge, 256 floats = 2 float4 per lane
// ---------------------------------------------------------------------------
__global__ __launch_bounds__(256) void k_scatter2(const int* __restrict__ src,
                                                  const int* __restrict__ dst) {
    int warp = (blockIdx.x * blockDim.x + threadIdx.x) >> 5;
    int lane = threadIdx.x & 31;
    if (warp >= NE2) return;
    int s = __ldg(src + warp);
    int d = __ldg(dst + warp);
    const float4* hr = (const float4*)(g_h1 + (size_t)s * DH);
    float4 v0 = hr[lane];
    float4 v1 = hr[lane + 32];
    float* base = g_agg2 + (size_t)d * DH;
    red_add_v4(base + lane * 4, v0);
    red_add_v4(base + (lane + 32) * 4, v1);
    if (lane == 0) atomicAdd(g_cnt2 + d, 1.0f);
}

__global__ void k_inv2() {
    int i = blockIdx.x * blockDim.x + threadIdx.x;
    if (i < NN2) g_inv2[i] = 1.0f / fmaxf(g_cnt2[i], 1.0f);
}

// ---------------------------------------------------------------------------
// 4) GEMM2 + fused log_softmax (fp32, unchanged from passing R6 kernel)
// ---------------------------------------------------------------------------
__global__ __launch_bounds__(256, 4) void k_gemm2(const float* __restrict__ Wl,
                                                  const float* __restrict__ Wr,
                                                  const float* __restrict__ bias,
                                                  float* __restrict__ out) {
    __shared__ float As[2][16][68];
    __shared__ float Bs[2][16][64];

    const int m0 = blockIdx.x * 64;
    const int tid = threadIdx.x;
    const int tx = tid & 15;
    const int ty = tid >> 4;
    const int arow = tid >> 2;      // 0..63
    const int acol = (tid & 3) * 4; // 0,4,8,12

    float acc[4][4];
#pragma unroll
    for (int i = 0; i < 4; ++i)
#pragma unroll
        for (int j = 0; j < 4; ++j) acc[i][j] = 0.f;

    const int m = m0 + arow;
    const bool mok = (m < NN2);
    const float sc = mok ? g_inv2[m] : 0.f;

    float4 ra, rb;
    auto load_tile = [&](int kt) {
        const int kbase = kt * 16;
        const bool first = (kbase < DH);
        const int kk = first ? kbase : (kbase - DH);
        float4 v = make_float4(0.f, 0.f, 0.f, 0.f);
        if (mok) {
            if (first) {
                v = *(const float4*)(g_agg2 + (size_t)m * DH + kk + acol);
                v.x *= sc; v.y *= sc; v.z *= sc; v.w *= sc;
            } else {
                v = *(const float4*)(g_h1 + (size_t)m * DH + kk + acol);
            }
        }
        ra = v;
        const float* W = first ? Wl : Wr;
        rb = __ldg((const float4*)(W + (size_t)arow * DH + kk + acol));
    };
    auto store_tile = [&](int buf) {
        As[buf][acol + 0][arow] = ra.x;
        As[buf][acol + 1][arow] = ra.y;
        As[buf][acol + 2][arow] = ra.z;
        As[buf][acol + 3][arow] = ra.w;
        Bs[buf][acol + 0][arow] = rb.x;
        Bs[buf][acol + 1][arow] = rb.y;
        Bs[buf][acol + 2][arow] = rb.z;
        Bs[buf][acol + 3][arow] = rb.w;
    };

    load_tile(0);
    store_tile(0);
    __syncthreads();

    for (int kt = 0; kt < 32; ++kt) {
        const int buf = kt & 1;
        if (kt < 31) load_tile(kt + 1);

#pragma unroll
        for (int k = 0; k < 16; ++k) {
            float a[4], b[4];
            *(float4*)a = *(const float4*)&As[buf][k][ty * 4];
            *(float4*)b = *(const float4*)&Bs[buf][k][tx * 4];
#pragma unroll
            for (int i = 0; i < 4; ++i)
#pragma unroll
                for (int j = 0; j < 4; ++j)
                    acc[i][j] += a[i] * b[j];
        }

        if (kt < 31) {
            store_tile(buf ^ 1);
            __syncthreads();
        }
    }

    // ---- epilogue: bias, then fused log_softmax over the 64 columns ----
    float bv[4];
#pragma unroll
    for (int j = 0; j < 4; ++j) bv[j] = __ldg(bias + tx * 4 + j);

    float vout[4][4];
#pragma unroll
    for (int i = 0; i < 4; ++i)
#pragma unroll
        for (int j = 0; j < 4; ++j) vout[i][j] = acc[i][j] + bv[j];

    __syncthreads();                       // done with As/Bs; reuse as scratch
    float* red = (float*)As;               // needs 64*17 = 1088 floats (< 2176)

    float mx[4];
#pragma unroll
    for (int i = 0; i < 4; ++i) {
        float v = fmaxf(fmaxf(vout[i][0], vout[i][1]),
                        fmaxf(vout[i][2], vout[i][3]));
        red[(ty * 4 + i) * 17 + tx] = v;
    }
    __syncthreads();
#pragma unroll
    for (int i = 0; i < 4; ++i) {
        float v = -3.402823466e38f;
        const float* rr = red + (ty * 4 + i) * 17;
#pragma unroll
        for (int t = 0; t < 16; ++t) v = fmaxf(v, rr[t]);
        mx[i] = v;
    }
    __syncthreads();

    float lse[4];
#pragma unroll
    for (int i = 0; i < 4; ++i) {
        float s = __expf(vout[i][0] - mx[i]) + __expf(vout[i][1] - mx[i])
                + __expf(vout[i][2] - mx[i]) + __expf(vout[i][3] - mx[i]);
        red[(ty * 4 + i) * 17 + tx] = s;
    }
    __syncthreads();
#pragma unroll
    for (int i = 0; i < 4; ++i) {
        float s = 0.f;
        const float* rr = red + (ty * 4 + i) * 17;
#pragma unroll
        for (int t = 0; t < 16; ++t) s += rr[t];
        lse[i] = mx[i] + logf(s);
    }

#pragma unroll
    for (int i = 0; i < 4; ++i) {
        int mm = m0 + ty * 4 + i;
        if (mm >= NN2) continue;
        float4 o;
        o.x = vout[i][0] - lse[i];
        o.y = vout[i][1] - lse[i];
        o.z = vout[i][2] - lse[i];
        o.w = vout[i][3] - lse[i];
        *(float4*)(out + (size_t)mm * DOUT + tx * 4) = o;
    }
}

// ---------------------------------------------------------------------------
// launch
// ---------------------------------------------------------------------------
extern "C" void kernel_launch(void* const* d_in, const int* in_sizes, int n_in,
                              void* d_out, int out_size) {
    const float* x    = (const float*)d_in[0];
    const int*   src1 = (const int*)d_in[1];
    const int*   dst1 = (const int*)d_in[2];
    const int*   src2 = (const int*)d_in[3];
    const int*   dst2 = (const int*)d_in[4];
    const float* Wl1  = (const float*)d_in[5];
    const float* bl1  = (const float*)d_in[6];
    const float* Wr1  = (const float*)d_in[7];
    const float* Wl2  = (const float*)d_in[8];
    const float* bl2  = (const float*)d_in[9];
    const float* Wr2  = (const float*)d_in[10];
    float* out = (float*)d_out;

    cudaFuncSetAttribute(k_gemm1, cudaFuncAttributeMaxDynamicSharedMemorySize,
                         SMEM1_BYTES);

    k_init<<<4096, 256>>>();
    k_scatter1<<<NE1 / 8, 256>>>(x, src1, dst1);          // 1 warp/edge
    k_inv1<<<(NN1 + 255) / 256, 256>>>();
    k_gemm1<<<(NN1 + BM1 - 1) / BM1, 256, SMEM1_BYTES>>>(x, Wl1, Wr1, bl1);
    k_scatter2<<<NE2 / 8, 256>>>(src2, dst2);
    k_inv2<<<(NN2 + 255) / 256, 256>>>();
    k_gemm2<<<(NN2 + 63) / 64, 256>>>(Wl2, Wr2, bl2, out);
}

// round 9
// speedup vs baseline: 1.4507x; 1.1442x over previous
#include <cuda_runtime.h>
#include <cuda_bf16.h>
#include <cstdint>

// Problem dims (fixed by the dataset)
#define NN0   200000
#define NN1   100000
#define NN2   20000
#define NE1   1600000
#define NE2   320000
#define DIN   128
#define DH    256
#define DOUT  64

// GEMM1 tiling (bf16 tensor core)
#define BM1   64
#define BN1   256          // = DH: single n-block, A read once
#define BK1   32           // bf16 k per tile; row = 64 bytes = 4 x 16B chunks
#define A_TILE_B  (BM1 * 64)        // 4096 B
#define B_TILE_B  (BN1 * 64)        // 16384 B

// ---------------------------------------------------------------------------
// Scratch (static __device__ globals — no allocation allowed)
// ---------------------------------------------------------------------------
__device__ float g_agg1[(size_t)NN1 * DIN];   // 51.2 MB
__device__ float g_cnt1[NN1];
__device__ float g_h1[(size_t)NN1 * DH];      // 102.4 MB
__device__ float g_agg2[(size_t)NN2 * DH];    // 20.5 MB
__device__ float g_cnt2[NN2];
__device__ float g_inv2[NN2];

// bf16 staging for GEMM1 (+64 rows padding so the last tile never faults)
__device__ __align__(16) __nv_bfloat16 g_agg1b[(size_t)(NN1 + BM1) * DIN];
__device__ __align__(16) __nv_bfloat16 g_xb[(size_t)(NN1 + BM1) * DIN];
__device__ __align__(16) __nv_bfloat16 g_Wl1b[DH * DIN];
__device__ __align__(16) __nv_bfloat16 g_Wr1b[DH * DIN];

// ---------------------------------------------------------------------------
// 0) zero the accumulators (must happen every replay — graph is re-run)
// ---------------------------------------------------------------------------
__global__ void k_init() {
    int i = blockIdx.x * blockDim.x + threadIdx.x;
    int stride = gridDim.x * blockDim.x;
    float4 z = make_float4(0.f, 0.f, 0.f, 0.f);
    for (int j = i; j < (NN1 * DIN) / 4; j += stride) ((float4*)g_agg1)[j] = z;
    for (int j = i; j < (NN2 * DH) / 4; j += stride) ((float4*)g_agg2)[j] = z;
    for (int j = i; j < NN1; j += stride) g_cnt1[j] = 0.f;
    for (int j = i; j < NN2; j += stride) g_cnt2[j] = 0.f;
}

// ---------------------------------------------------------------------------
// helpers
// ---------------------------------------------------------------------------
__device__ __forceinline__ void red_add_v4(float* p, float4 v) {
    asm volatile("red.global.add.v4.f32 [%0], {%1,%2,%3,%4};"
                 :: "l"(p), "f"(v.x), "f"(v.y), "f"(v.z), "f"(v.w)
                 : "memory");
}

__device__ __forceinline__ void cp_async16(uint32_t smem_dst, const void* gmem_src) {
    asm volatile("cp.async.ca.shared.global [%0], [%1], 16;"
                 :: "r"(smem_dst), "l"(gmem_src) : "memory");
}

__device__ __forceinline__ void ldsm_x4(uint32_t& r0, uint32_t& r1,
                                        uint32_t& r2, uint32_t& r3, uint32_t a) {
    asm volatile("ldmatrix.sync.aligned.m8n8.x4.shared.b16 {%0,%1,%2,%3}, [%4];"
                 : "=r"(r0), "=r"(r1), "=r"(r2), "=r"(r3) : "r"(a));
}

__device__ __forceinline__ void mma_bf16(float* c, const uint32_t* a,
                                         uint32_t b0, uint32_t b1) {
    asm volatile(
        "mma.sync.aligned.m16n8k16.row.col.f32.bf16.bf16.f32 "
        "{%0,%1,%2,%3}, {%4,%5,%6,%7}, {%8,%9}, {%0,%1,%2,%3};"
        : "+f"(c[0]), "+f"(c[1]), "+f"(c[2]), "+f"(c[3])
        : "r"(a[0]), "r"(a[1]), "r"(a[2]), "r"(a[3]), "r"(b0), "r"(b1));
}

// ---------------------------------------------------------------------------
// 1) scatter-add layer 1: one warp per edge, 32 lanes x float4 = 128 floats
// ---------------------------------------------------------------------------
__global__ __launch_bounds__(256) void k_scatter1(const float* __restrict__ x,
                                                  const int* __restrict__ src,
                                                  const int* __restrict__ dst) {
    int warp = (blockIdx.x * blockDim.x + threadIdx.x) >> 5;
    int lane = threadIdx.x & 31;
    if (warp >= NE1) return;
    int s = __ldg(src + warp);
    int d = __ldg(dst + warp);
    const float4* xr = (const float4*)(x + (size_t)s * DIN);
    float4 v = __ldg(xr + lane);
    red_add_v4(g_agg1 + (size_t)d * DIN + lane * 4, v);
    if (lane == 0) atomicAdd(g_cnt1 + d, 1.0f);
}

// ---------------------------------------------------------------------------
// 1b) conversions to bf16 for GEMM1
// ---------------------------------------------------------------------------
__global__ void k_conv_w(const float* __restrict__ Wl, const float* __restrict__ Wr) {
    int i = blockIdx.x * blockDim.x + threadIdx.x;   // 8192 threads, 4 elems each
    if (i >= (DH * DIN) / 4) return;
    float4 a = __ldg((const float4*)Wl + i);
    float4 b = __ldg((const float4*)Wr + i);
    ((__nv_bfloat162*)g_Wl1b)[i * 2 + 0] = __floats2bfloat162_rn(a.x, a.y);
    ((__nv_bfloat162*)g_Wl1b)[i * 2 + 1] = __floats2bfloat162_rn(a.z, a.w);
    ((__nv_bfloat162*)g_Wr1b)[i * 2 + 0] = __floats2bfloat162_rn(b.x, b.y);
    ((__nv_bfloat162*)g_Wr1b)[i * 2 + 1] = __floats2bfloat162_rn(b.z, b.w);
}

// warp per node row: agg1*inv -> bf16, x -> bf16
__global__ __launch_bounds__(256) void k_conv_a(const float* __restrict__ x) {
    int row = (blockIdx.x * blockDim.x + threadIdx.x) >> 5;
    int lane = threadIdx.x & 31;
    if (row >= NN1) return;
    float inv = 1.0f / fmaxf(__ldg(g_cnt1 + row), 1.0f);
    float4 va = *(const float4*)(g_agg1 + (size_t)row * DIN + lane * 4);
    float4 vx = __ldg((const float4*)(x + (size_t)row * DIN + lane * 4));
    __nv_bfloat162* pa = (__nv_bfloat162*)(g_agg1b + (size_t)row * DIN) + lane * 2;
    __nv_bfloat162* px = (__nv_bfloat162*)(g_xb + (size_t)row * DIN) + lane * 2;
    pa[0] = __floats2bfloat162_rn(va.x * inv, va.y * inv);
    pa[1] = __floats2bfloat162_rn(va.z * inv, va.w * inv);
    px[0] = __floats2bfloat162_rn(vx.x, vx.y);
    px[1] = __floats2bfloat162_rn(vx.z, vx.w);
}

// ---------------------------------------------------------------------------
// 2) GEMM1 (bf16 tensor core + ldmatrix + cp.async):
//    h1 = relu( agg1b @ Wl1b^T + xb @ Wr1b^T + b_l1 ), virtual K=256.
//    BM=64, BN=256, BK=32(bf16). 8 warps (2m x 4n), warp tile 32x64.
//    Smem rows are 64B = 4 x 16B chunks, swizzled chunk ^= (row>>1)&3 ->
//    conflict-free for both cp.async targets and all ldmatrix phases.
// ---------------------------------------------------------------------------
__global__ __launch_bounds__(256, 2) void k_gemm1(const float* __restrict__ bias) {
    __shared__ __align__(16) char smem[2 * (A_TILE_B + B_TILE_B)];  // 40 KB
    const uint32_t sbase = (uint32_t)__cvta_generic_to_shared(smem);
    const uint32_t aBase[2] = {sbase, sbase + A_TILE_B};
    const uint32_t bBase[2] = {sbase + 2 * A_TILE_B, sbase + 2 * A_TILE_B + B_TILE_B};

    const int tid  = threadIdx.x;
    const int warp = tid >> 5;
    const int lane = tid & 31;
    const int wm   = (warp & 1) * 32;
    const int wn   = (warp >> 1) * 64;
    const int m0   = blockIdx.x * BM1;

    // cp.async mapping: A -> thread t: row t&63, chunk t>>6 (1 chunk)
    //                   B -> thread t: row t, chunks 0..3
    const int arow = tid & 63;
    const int achk = tid >> 6;
    const uint32_t a_dst_off = arow * 64 + 16 * (achk ^ ((arow >> 1) & 3));
    uint32_t b_dst_off[4];
#pragma unroll
    for (int c = 0; c < 4; ++c)
        b_dst_off[c] = tid * 64 + 16 * (c ^ ((tid >> 1) & 3));

    auto cp_tile = [&](int kt, int buf) {
        const int kk = (kt * BK1) & (DIN - 1);
        const __nv_bfloat16* Asrc = ((kt < 4) ? g_agg1b : g_xb)
                                    + (size_t)(m0 + arow) * DIN + kk + achk * 8;
        cp_async16(aBase[buf] + a_dst_off, Asrc);
        const __nv_bfloat16* W = (kt < 4) ? g_Wl1b : g_Wr1b;
        const __nv_bfloat16* Bsrc = W + (size_t)tid * DIN + kk;
#pragma unroll
        for (int c = 0; c < 4; ++c)
            cp_async16(bBase[buf] + b_dst_off[c], Bsrc + c * 8);
        asm volatile("cp.async.commit_group;" ::: "memory");
    };

    // ldmatrix lane addressing (row part constant per thread)
    uint32_t aoff[2]; int asel[2];
#pragma unroll
    for (int mt = 0; mt < 2; ++mt) {
        int r = wm + mt * 16 + (lane & 7) + ((lane >> 3) & 1) * 8;
        aoff[mt] = r * 64;
        asel[mt] = (r >> 1) & 3;
    }
    const int a_ck = lane >> 4;            // +0 / +1 chunk within k16
    uint32_t boff[4]; int bsel[4];
#pragma unroll
    for (int ntp = 0; ntp < 4; ++ntp) {
        int n = wn + ntp * 16 + (lane & 7) + ((lane >> 4) & 1) * 8;
        boff[ntp] = n * 64;
        bsel[ntp] = (n >> 1) & 3;
    }
    const int b_ck = (lane >> 3) & 1;

    float acc[2][8][4];
#pragma unroll
    for (int mt = 0; mt < 2; ++mt)
#pragma unroll
        for (int nt = 0; nt < 8; ++nt)
#pragma unroll
            for (int q = 0; q < 4; ++q) acc[mt][nt][q] = 0.f;

    cp_tile(0, 0);
    asm volatile("cp.async.wait_group 0;" ::: "memory");
    __syncthreads();

    for (int kt = 0; kt < 8; ++kt) {
        const int buf = kt & 1;
        if (kt < 7) cp_tile(kt + 1, buf ^ 1);     // async during MMAs

#pragma unroll
        for (int k16 = 0; k16 < 2; ++k16) {
            uint32_t af[2][4];
#pragma unroll
            for (int mt = 0; mt < 2; ++mt)
                ldsm_x4(af[mt][0], af[mt][1], af[mt][2], af[mt][3],
                        aBase[buf] + aoff[mt]
                        + 16 * ((k16 * 2 + a_ck) ^ asel[mt]));
#pragma unroll
            for (int ntp = 0; ntp < 4; ++ntp) {
                uint32_t b0, b1, b2, b3;
                ldsm_x4(b0, b1, b2, b3,
                        bBase[buf] + boff[ntp]
                        + 16 * ((k16 * 2 + b_ck) ^ bsel[ntp]));
                mma_bf16(acc[0][ntp * 2 + 0], af[0], b0, b1);
                mma_bf16(acc[1][ntp * 2 + 0], af[1], b0, b1);
                mma_bf16(acc[0][ntp * 2 + 1], af[0], b2, b3);
                mma_bf16(acc[1][ntp * 2 + 1], af[1], b2, b3);
            }
        }

        if (kt < 7) {
            asm volatile("cp.async.wait_group 0;" ::: "memory");
            __syncthreads();
        }
    }

    // ---- epilogue: bias + relu -> g_h1 (float2 stores, mma C layout) ----
    const int l4 = lane >> 2;
    const int la3 = lane & 3;
#pragma unroll
    for (int mt = 0; mt < 2; ++mt) {
        const int r0 = m0 + wm + mt * 16 + l4;
#pragma unroll
        for (int half = 0; half < 2; ++half) {
            const int m = r0 + half * 8;
            if (m >= NN1) continue;
            float* rowp = g_h1 + (size_t)m * DH;
#pragma unroll
            for (int nt = 0; nt < 8; ++nt) {
                const int ncol = wn + nt * 8 + 2 * la3;
                float2 o;
                o.x = fmaxf(acc[mt][nt][half * 2 + 0] + __ldg(bias + ncol), 0.f);
                o.y = fmaxf(acc[mt][nt][half * 2 + 1] + __ldg(bias + ncol + 1), 0.f);
                *(float2*)(rowp + ncol) = o;
            }
        }
    }
}

// ---------------------------------------------------------------------------
// 3) scatter-add layer 2: warp per edge, 256 floats = 2 float4 per lane
// ---------------------------------------------------------------------------
__global__ __launch_bounds__(256) void k_scatter2(const int* __restrict__ src,
                                                  const int* __restrict__ dst) {
    int warp = (blockIdx.x * blockDim.x + threadIdx.x) >> 5;
    int lane = threadIdx.x & 31;
    if (warp >= NE2) return;
    int s = __ldg(src + warp);
    int d = __ldg(dst + warp);
    const float4* hr = (const float4*)(g_h1 + (size_t)s * DH);
    float4 v0 = hr[lane];
    float4 v1 = hr[lane + 32];
    float* base = g_agg2 + (size_t)d * DH;
    red_add_v4(base + lane * 4, v0);
    red_add_v4(base + (lane + 32) * 4, v1);
    if (lane == 0) atomicAdd(g_cnt2 + d, 1.0f);
}

__global__ void k_inv2() {
    int i = blockIdx.x * blockDim.x + threadIdx.x;
    if (i < NN2) g_inv2[i] = 1.0f / fmaxf(g_cnt2[i], 1.0f);
}

// ---------------------------------------------------------------------------
// 4) GEMM2 + fused log_softmax (fp32, unchanged — keeps layer-2 exact)
// ---------------------------------------------------------------------------
__global__ __launch_bounds__(256, 4) void k_gemm2(const float* __restrict__ Wl,
                                                  const float* __restrict__ Wr,
                                                  const float* __restrict__ bias,
                                                  float* __restrict__ out) {
    __shared__ float As[2][16][68];
    __shared__ float Bs[2][16][64];

    const int m0 = blockIdx.x * 64;
    const int tid = threadIdx.x;
    const int tx = tid & 15;
    const int ty = tid >> 4;
    const int arow = tid >> 2;
    const int acol = (tid & 3) * 4;

    float acc[4][4];
#pragma unroll
    for (int i = 0; i < 4; ++i)
#pragma unroll
        for (int j = 0; j < 4; ++j) acc[i][j] = 0.f;

    const int m = m0 + arow;
    const bool mok = (m < NN2);
    const float sc = mok ? g_inv2[m] : 0.f;

    float4 ra, rb;
    auto load_tile = [&](int kt) {
        const int kbase = kt * 16;
        const bool first = (kbase < DH);
        const int kk = first ? kbase : (kbase - DH);
        float4 v = make_float4(0.f, 0.f, 0.f, 0.f);
        if (mok) {
            if (first) {
                v = *(const float4*)(g_agg2 + (size_t)m * DH + kk + acol);
                v.x *= sc; v.y *= sc; v.z *= sc; v.w *= sc;
            } else {
                v = *(const float4*)(g_h1 + (size_t)m * DH + kk + acol);
            }
        }
        ra = v;
        const float* W = first ? Wl : Wr;
        rb = __ldg((const float4*)(W + (size_t)arow * DH + kk + acol));
    };
    auto store_tile = [&](int buf) {
        As[buf][acol + 0][arow] = ra.x;
        As[buf][acol + 1][arow] = ra.y;
        As[buf][acol + 2][arow] = ra.z;
        As[buf][acol + 3][arow] = ra.w;
        Bs[buf][acol + 0][arow] = rb.x;
        Bs[buf][acol + 1][arow] = rb.y;
        Bs[buf][acol + 2][arow] = rb.z;
        Bs[buf][acol + 3][arow] = rb.w;
    };

    load_tile(0);
    store_tile(0);
    __syncthreads();

    for (int kt = 0; kt < 32; ++kt) {
        const int buf = kt & 1;
        if (kt < 31) load_tile(kt + 1);

#pragma unroll
        for (int k = 0; k < 16; ++k) {
            float a[4], b[4];
            *(float4*)a = *(const float4*)&As[buf][k][ty * 4];
            *(float4*)b = *(const float4*)&Bs[buf][k][tx * 4];
#pragma unroll
            for (int i = 0; i < 4; ++i)
#pragma unroll
                for (int j = 0; j < 4; ++j)
                    acc[i][j] += a[i] * b[j];
        }

        if (kt < 31) {
            store_tile(buf ^ 1);
            __syncthreads();
        }
    }

    float bv[4];
#pragma unroll
    for (int j = 0; j < 4; ++j) bv[j] = __ldg(bias + tx * 4 + j);

    float vout[4][4];
#pragma unroll
    for (int i = 0; i < 4; ++i)
#pragma unroll
        for (int j = 0; j < 4; ++j) vout[i][j] = acc[i][j] + bv[j];

    __syncthreads();
    float* red = (float*)As;

    float mx[4];
#pragma unroll
    for (int i = 0; i < 4; ++i) {
        float v = fmaxf(fmaxf(vout[i][0], vout[i][1]),
                        fmaxf(vout[i][2], vout[i][3]));
        red[(ty * 4 + i) * 17 + tx] = v;
    }
    __syncthreads();
#pragma unroll
    for (int i = 0; i < 4; ++i) {
        float v = -3.402823466e38f;
        const float* rr = red + (ty * 4 + i) * 17;
#pragma unroll
        for (int t = 0; t < 16; ++t) v = fmaxf(v, rr[t]);
        mx[i] = v;
    }
    __syncthreads();

    float lse[4];
#pragma unroll
    for (int i = 0; i < 4; ++i) {
        float s = __expf(vout[i][0] - mx[i]) + __expf(vout[i][1] - mx[i])
                + __expf(vout[i][2] - mx[i]) + __expf(vout[i][3] - mx[i]);
        red[(ty * 4 + i) * 17 + tx] = s;
    }
    __syncthreads();
#pragma unroll
    for (int i = 0; i < 4; ++i) {
        float s = 0.f;
        const float* rr = red + (ty * 4 + i) * 17;
#pragma unroll
        for (int t = 0; t < 16; ++t) s += rr[t];
        lse[i] = mx[i] + logf(s);
    }

#pragma unroll
    for (int i = 0; i < 4; ++i) {
        int mm = m0 + ty * 4 + i;
        if (mm >= NN2) continue;
        float4 o;
        o.x = vout[i][0] - lse[i];
        o.y = vout[i][1] - lse[i];
        o.z = vout[i][2] - lse[i];
        o.w = vout[i][3] - lse[i];
        *(float4*)(out + (size_t)mm * DOUT + tx * 4) = o;
    }
}

// ---------------------------------------------------------------------------
// launch
// ---------------------------------------------------------------------------
extern "C" void kernel_launch(void* const* d_in, const int* in_sizes, int n_in,
                              void* d_out, int out_size) {
    const float* x    = (const float*)d_in[0];
    const int*   src1 = (const int*)d_in[1];
    const int*   dst1 = (const int*)d_in[2];
    const int*   src2 = (const int*)d_in[3];
    const int*   dst2 = (const int*)d_in[4];
    const float* Wl1  = (const float*)d_in[5];
    const float* bl1  = (const float*)d_in[6];
    const float* Wr1  = (const float*)d_in[7];
    const float* Wl2  = (const float*)d_in[8];
    const float* bl2  = (const float*)d_in[9];
    const float* Wr2  = (const float*)d_in[10];
    float* out = (float*)d_out;

    k_init<<<4096, 256>>>();
    k_conv_w<<<32, 256>>>(Wl1, Wr1);
    k_scatter1<<<NE1 / 8, 256>>>(x, src1, dst1);          // 1 warp/edge
    k_conv_a<<<(NN1 * 32 + 255) / 256, 256>>>(x);
    k_gemm1<<<(NN1 + BM1 - 1) / BM1, 256>>>(bl1);
    k_scatter2<<<NE2 / 8, 256>>>(src2, dst2);
    k_inv2<<<(NN2 + 255) / 256, 256>>>();
    k_gemm2<<<(NN2 + 63) / 64, 256>>>(Wl2, Wr2, bl2, out);
}

// round 14
// speedup vs baseline: 2.1101x; 1.4545x over previous
#include <cuda_runtime.h>
#include <cuda_bf16.h>
#include <cstdint>

// Problem dims (fixed by the dataset)
#define NN0   200000
#define NN1   100000
#define NN2   20000
#define NE1   1600000
#define NE2   320000
#define DIN   128
#define DH    256
#define DOUT  64

// GEMM1 tiling (bf16 tensor core)
#define BM1   64
#define BN1   256
#define BK1   32
#define A_TILE_B  (BM1 * 64)        // 4096 B
#define B_TILE_B  (BN1 * 64)        // 16384 B

// ---------------------------------------------------------------------------
// Scratch (static __device__ globals — no allocation allowed).
// NOTE: these are referenced ONLY from device code. Passing their addresses
// from host code is invalid (host shadow symbol) — that was the R10/R11 bug.
// ---------------------------------------------------------------------------
__device__ float g_h1[(size_t)NN1 * DH];      // 102.4 MB
__device__ float g_agg2[(size_t)NN2 * DH];    // 20.5 MB

// CSR build
__device__ int g_cnt1i[NN1];
__device__ int g_off1[NN1];    // segment start (immutable after alloc)
__device__ int g_cur1[NN1];    // bucket cursor (mutated)
__device__ int g_cnt2i[NN2];
__device__ int g_off2[NN2];
__device__ int g_cur2[NN2];
__device__ int g_tot1;
__device__ int g_tot2;
__device__ int g_eidx1[NE1];                  // 6.4 MB
__device__ int g_eidx2[NE2];                  // 1.28 MB

// bf16 staging for GEMM1 (+64 rows padding so the last tile never faults)
__device__ __align__(16) __nv_bfloat16 g_agg1b[(size_t)(NN1 + BM1) * DIN];
__device__ __align__(16) __nv_bfloat16 g_xb[(size_t)(NN1 + BM1) * DIN];
__device__ __align__(16) __nv_bfloat16 g_Wl1b[DH * DIN];
__device__ __align__(16) __nv_bfloat16 g_Wr1b[DH * DIN];

// ---------------------------------------------------------------------------
// helpers
// ---------------------------------------------------------------------------
__device__ __forceinline__ void cp_async16(uint32_t smem_dst, const void* gmem_src) {
    asm volatile("cp.async.ca.shared.global [%0], [%1], 16;"
                 :: "r"(smem_dst), "l"(gmem_src) : "memory");
}

__device__ __forceinline__ void ldsm_x4(uint32_t& r0, uint32_t& r1,
                                        uint32_t& r2, uint32_t& r3, uint32_t a) {
    asm volatile("ldmatrix.sync.aligned.m8n8.x4.shared.b16 {%0,%1,%2,%3}, [%4];"
                 : "=r"(r0), "=r"(r1), "=r"(r2), "=r"(r3) : "r"(a));
}

__device__ __forceinline__ void mma_bf16(float* c, const uint32_t* a,
                                         uint32_t b0, uint32_t b1) {
    asm volatile(
        "mma.sync.aligned.m16n8k16.row.col.f32.bf16.bf16.f32 "
        "{%0,%1,%2,%3}, {%4,%5,%6,%7}, {%8,%9}, {%0,%1,%2,%3};"
        : "+f"(c[0]), "+f"(c[1]), "+f"(c[2]), "+f"(c[3])
        : "r"(a[0]), "r"(a[1]), "r"(a[2]), "r"(a[3]), "r"(b0), "r"(b1));
}

// ---------------------------------------------------------------------------
// CSR build: zero -> hist -> warp-atomic alloc -> bucket
// ---------------------------------------------------------------------------
__global__ void k_zero() {
    int i = blockIdx.x * blockDim.x + threadIdx.x;
    if (i < NN1) g_cnt1i[i] = 0;
    if (i < NN2) g_cnt2i[i] = 0;
    if (i == 0) { g_tot1 = 0; g_tot2 = 0; }
}

__global__ void k_hist(const int* __restrict__ dst1, const int* __restrict__ dst2) {
    int e = blockIdx.x * blockDim.x + threadIdx.x;
    if (e < NE1) atomicAdd(&g_cnt1i[__ldg(dst1 + e)], 1);
    if (e < NE2) atomicAdd(&g_cnt2i[__ldg(dst2 + e)], 1);
}

// Warp-level segment allocator: inclusive shfl-scan of counts within the warp,
// one atomicAdd on the global counter per warp, distribute bases via shfl.
// Segment placement is run-varying, but each node owns a private contiguous
// range of the correct length — sums are over the same multiset.
__global__ void k_alloc1() {
    int i = blockIdx.x * blockDim.x + threadIdx.x;
    int lane = threadIdx.x & 31;
    int c = (i < NN1) ? g_cnt1i[i] : 0;
    int s = c;
#pragma unroll
    for (int o = 1; o < 32; o <<= 1) {
        int y = __shfl_up_sync(0xffffffffu, s, o);
        if (lane >= o) s += y;
    }
    int wsum = __shfl_sync(0xffffffffu, s, 31);
    int base = 0;
    if (lane == 31) base = atomicAdd(&g_tot1, wsum);
    base = __shfl_sync(0xffffffffu, base, 31);
    int start = base + s - c;
    if (i < NN1) { g_off1[i] = start; g_cur1[i] = start; }
}

__global__ void k_alloc2() {
    int i = blockIdx.x * blockDim.x + threadIdx.x;
    int lane = threadIdx.x & 31;
    int c = (i < NN2) ? g_cnt2i[i] : 0;
    int s = c;
#pragma unroll
    for (int o = 1; o < 32; o <<= 1) {
        int y = __shfl_up_sync(0xffffffffu, s, o);
        if (lane >= o) s += y;
    }
    int wsum = __shfl_sync(0xffffffffu, s, 31);
    int base = 0;
    if (lane == 31) base = atomicAdd(&g_tot2, wsum);
    base = __shfl_sync(0xffffffffu, base, 31);
    int start = base + s - c;
    if (i < NN2) { g_off2[i] = start; g_cur2[i] = start; }
}

__global__ void k_bucket1(const int* __restrict__ src, const int* __restrict__ dst) {
    int e = blockIdx.x * blockDim.x + threadIdx.x;
    if (e >= NE1) return;
    int p = atomicAdd(&g_cur1[__ldg(dst + e)], 1);
    g_eidx1[p] = __ldg(src + e);
}
__global__ void k_bucket2(const int* __restrict__ src, const int* __restrict__ dst) {
    int e = blockIdx.x * blockDim.x + threadIdx.x;
    if (e >= NE2) return;
    int p = atomicAdd(&g_cur2[__ldg(dst + e)], 1);
    g_eidx2[p] = __ldg(src + e);
}

// ---------------------------------------------------------------------------
// aggregation 1: warp per dst node, fp32 register acc, writes bf16 (inv applied)
// ---------------------------------------------------------------------------
__global__ __launch_bounds__(256) void k_agg1(const float* __restrict__ x) {
    int d = (blockIdx.x * blockDim.x + threadIdx.x) >> 5;
    int lane = threadIdx.x & 31;
    if (d >= NN1) return;
    const int cnt = g_cnt1i[d];
    const int start = g_off1[d];
    float4 acc = make_float4(0.f, 0.f, 0.f, 0.f);
    int i = 0;
    for (; i + 2 <= cnt; i += 2) {
        int s0 = __ldg(g_eidx1 + start + i);
        int s1 = __ldg(g_eidx1 + start + i + 1);
        float4 a = __ldg((const float4*)(x + (size_t)s0 * DIN) + lane);
        float4 b = __ldg((const float4*)(x + (size_t)s1 * DIN) + lane);
        acc.x += a.x + b.x; acc.y += a.y + b.y;
        acc.z += a.z + b.z; acc.w += a.w + b.w;
    }
    if (i < cnt) {
        int s0 = __ldg(g_eidx1 + start + i);
        float4 a = __ldg((const float4*)(x + (size_t)s0 * DIN) + lane);
        acc.x += a.x; acc.y += a.y; acc.z += a.z; acc.w += a.w;
    }
    const float inv = 1.0f / fmaxf((float)cnt, 1.0f);
    __nv_bfloat162* pa = (__nv_bfloat162*)(g_agg1b + (size_t)d * DIN) + lane * 2;
    pa[0] = __floats2bfloat162_rn(acc.x * inv, acc.y * inv);
    pa[1] = __floats2bfloat162_rn(acc.z * inv, acc.w * inv);
}

// ---------------------------------------------------------------------------
// conversions to bf16 for GEMM1
// ---------------------------------------------------------------------------
__global__ void k_conv_w(const float* __restrict__ Wl, const float* __restrict__ Wr) {
    int i = blockIdx.x * blockDim.x + threadIdx.x;
    if (i >= (DH * DIN) / 4) return;
    float4 a = __ldg((const float4*)Wl + i);
    float4 b = __ldg((const float4*)Wr + i);
    ((__nv_bfloat162*)g_Wl1b)[i * 2 + 0] = __floats2bfloat162_rn(a.x, a.y);
    ((__nv_bfloat162*)g_Wl1b)[i * 2 + 1] = __floats2bfloat162_rn(a.z, a.w);
    ((__nv_bfloat162*)g_Wr1b)[i * 2 + 0] = __floats2bfloat162_rn(b.x, b.y);
    ((__nv_bfloat162*)g_Wr1b)[i * 2 + 1] = __floats2bfloat162_rn(b.z, b.w);
}

__global__ void k_conv_x(const float* __restrict__ x) {
    int i = blockIdx.x * blockDim.x + threadIdx.x;   // over NN1*DIN/4
    if (i >= (NN1 * DIN) / 4) return;
    float4 v = __ldg((const float4*)x + i);
    ((__nv_bfloat162*)g_xb)[i * 2 + 0] = __floats2bfloat162_rn(v.x, v.y);
    ((__nv_bfloat162*)g_xb)[i * 2 + 1] = __floats2bfloat162_rn(v.z, v.w);
}

// ---------------------------------------------------------------------------
// GEMM1 (bf16 tensor core + ldmatrix + cp.async) — unchanged from R9 pass
// ---------------------------------------------------------------------------
__global__ __launch_bounds__(256, 2) void k_gemm1(const float* __restrict__ bias) {
    __shared__ __align__(16) char smem[2 * (A_TILE_B + B_TILE_B)];  // 40 KB
    const uint32_t sbase = (uint32_t)__cvta_generic_to_shared(smem);
    const uint32_t aBase[2] = {sbase, sbase + A_TILE_B};
    const uint32_t bBase[2] = {sbase + 2 * A_TILE_B, sbase + 2 * A_TILE_B + B_TILE_B};

    const int tid  = threadIdx.x;
    const int warp = tid >> 5;
    const int lane = tid & 31;
    const int wm   = (warp & 1) * 32;
    const int wn   = (warp >> 1) * 64;
    const int m0   = blockIdx.x * BM1;

    const int arow = tid & 63;
    const int achk = tid >> 6;
    const uint32_t a_dst_off = arow * 64 + 16 * (achk ^ ((arow >> 1) & 3));
    uint32_t b_dst_off[4];
#pragma unroll
    for (int c = 0; c < 4; ++c)
        b_dst_off[c] = tid * 64 + 16 * (c ^ ((tid >> 1) & 3));

    auto cp_tile = [&](int kt, int buf) {
        const int kk = (kt * BK1) & (DIN - 1);
        const __nv_bfloat16* Asrc = ((kt < 4) ? g_agg1b : g_xb)
                                    + (size_t)(m0 + arow) * DIN + kk + achk * 8;
        cp_async16(aBase[buf] + a_dst_off, Asrc);
        const __nv_bfloat16* W = (kt < 4) ? g_Wl1b : g_Wr1b;
        const __nv_bfloat16* Bsrc = W + (size_t)tid * DIN + kk;
#pragma unroll
        for (int c = 0; c < 4; ++c)
            cp_async16(bBase[buf] + b_dst_off[c], Bsrc + c * 8);
        asm volatile("cp.async.commit_group;" ::: "memory");
    };

    uint32_t aoff[2]; int asel[2];
#pragma unroll
    for (int mt = 0; mt < 2; ++mt) {
        int r = wm + mt * 16 + (lane & 7) + ((lane >> 3) & 1) * 8;
        aoff[mt] = r * 64;
        asel[mt] = (r >> 1) & 3;
    }
    const int a_ck = lane >> 4;
    uint32_t boff[4]; int bsel[4];
#pragma unroll
    for (int ntp = 0; ntp < 4; ++ntp) {
        int n = wn + ntp * 16 + (lane & 7) + ((lane >> 4) & 1) * 8;
        boff[ntp] = n * 64;
        bsel[ntp] = (n >> 1) & 3;
    }
    const int b_ck = (lane >> 3) & 1;

    float acc[2][8][4];
#pragma unroll
    for (int mt = 0; mt < 2; ++mt)
#pragma unroll
        for (int nt = 0; nt < 8; ++nt)
#pragma unroll
            for (int q = 0; q < 4; ++q) acc[mt][nt][q] = 0.f;

    cp_tile(0, 0);
    asm volatile("cp.async.wait_group 0;" ::: "memory");
    __syncthreads();

    for (int kt = 0; kt < 8; ++kt) {
        const int buf = kt & 1;
        if (kt < 7) cp_tile(kt + 1, buf ^ 1);

#pragma unroll
        for (int k16 = 0; k16 < 2; ++k16) {
            uint32_t af[2][4];
#pragma unroll
            for (int mt = 0; mt < 2; ++mt)
                ldsm_x4(af[mt][0], af[mt][1], af[mt][2], af[mt][3],
                        aBase[buf] + aoff[mt]
                        + 16 * ((k16 * 2 + a_ck) ^ asel[mt]));
#pragma unroll
            for (int ntp = 0; ntp < 4; ++ntp) {
                uint32_t b0, b1, b2, b3;
                ldsm_x4(b0, b1, b2, b3,
                        bBase[buf] + boff[ntp]
                        + 16 * ((k16 * 2 + b_ck) ^ bsel[ntp]));
                mma_bf16(acc[0][ntp * 2 + 0], af[0], b0, b1);
                mma_bf16(acc[1][ntp * 2 + 0], af[1], b0, b1);
                mma_bf16(acc[0][ntp * 2 + 1], af[0], b2, b3);
                mma_bf16(acc[1][ntp * 2 + 1], af[1], b2, b3);
            }
        }

        if (kt < 7) {
            asm volatile("cp.async.wait_group 0;" ::: "memory");
            __syncthreads();
        }
    }

    const int l4 = lane >> 2;
    const int la3 = lane & 3;
#pragma unroll
    for (int mt = 0; mt < 2; ++mt) {
        const int r0 = m0 + wm + mt * 16 + l4;
#pragma unroll
        for (int half = 0; half < 2; ++half) {
            const int m = r0 + half * 8;
            if (m >= NN1) continue;
            float* rowp = g_h1 + (size_t)m * DH;
#pragma unroll
            for (int nt = 0; nt < 8; ++nt) {
                const int ncol = wn + nt * 8 + 2 * la3;
                float2 o;
                o.x = fmaxf(acc[mt][nt][half * 2 + 0] + __ldg(bias + ncol), 0.f);
                o.y = fmaxf(acc[mt][nt][half * 2 + 1] + __ldg(bias + ncol + 1), 0.f);
                *(float2*)(rowp + ncol) = o;
            }
        }
    }
}

// ---------------------------------------------------------------------------
// aggregation 2: warp per dst node, writes fp32 agg2 with inv applied
// ---------------------------------------------------------------------------
__global__ __launch_bounds__(256) void k_agg2() {
    int d = (blockIdx.x * blockDim.x + threadIdx.x) >> 5;
    int lane = threadIdx.x & 31;
    if (d >= NN2) return;
    const int cnt = g_cnt2i[d];
    const int start = g_off2[d];
    float4 a0 = make_float4(0.f, 0.f, 0.f, 0.f);
    float4 a1 = a0;
    for (int i = 0; i < cnt; ++i) {
        int s = __ldg(g_eidx2 + start + i);
        const float4* hr = (const float4*)(g_h1 + (size_t)s * DH);
        float4 u = __ldg(hr + lane);
        float4 v = __ldg(hr + lane + 32);
        a0.x += u.x; a0.y += u.y; a0.z += u.z; a0.w += u.w;
        a1.x += v.x; a1.y += v.y; a1.z += v.z; a1.w += v.w;
    }
    const float inv = 1.0f / fmaxf((float)cnt, 1.0f);
    float4* base = (float4*)(g_agg2 + (size_t)d * DH);
    a0.x *= inv; a0.y *= inv; a0.z *= inv; a0.w *= inv;
    a1.x *= inv; a1.y *= inv; a1.z *= inv; a1.w *= inv;
    base[lane] = a0;
    base[lane + 32] = a1;
}

// ---------------------------------------------------------------------------
// GEMM2 + fused log_softmax (fp32; agg2 already mean-scaled)
// ---------------------------------------------------------------------------
__global__ __launch_bounds__(256, 4) void k_gemm2(const float* __restrict__ Wl,
                                                  const float* __restrict__ Wr,
                                                  const float* __restrict__ bias,
                                                  float* __restrict__ out) {
    __shared__ float As[2][16][68];
    __shared__ float Bs[2][16][64];

    const int m0 = blockIdx.x * 64;
    const int tid = threadIdx.x;
    const int tx = tid & 15;
    const int ty = tid >> 4;
    const int arow = tid >> 2;
    const int acol = (tid & 3) * 4;

    float acc[4][4];
#pragma unroll
    for (int i = 0; i < 4; ++i)
#pragma unroll
        for (int j = 0; j < 4; ++j) acc[i][j] = 0.f;

    const int m = m0 + arow;
    const bool mok = (m < NN2);

    float4 ra, rb;
    auto load_tile = [&](int kt) {
        const int kbase = kt * 16;
        const bool first = (kbase < DH);
        const int kk = first ? kbase : (kbase - DH);
        float4 v = make_float4(0.f, 0.f, 0.f, 0.f);
        if (mok) {
            if (first) v = *(const float4*)(g_agg2 + (size_t)m * DH + kk + acol);
            else       v = *(const float4*)(g_h1 + (size_t)m * DH + kk + acol);
        }
        ra = v;
        const float* W = first ? Wl : Wr;
        rb = __ldg((const float4*)(W + (size_t)arow * DH + kk + acol));
    };
    auto store_tile = [&](int buf) {
        As[buf][acol + 0][arow] = ra.x;
        As[buf][acol + 1][arow] = ra.y;
        As[buf][acol + 2][arow] = ra.z;
        As[buf][acol + 3][arow] = ra.w;
        Bs[buf][acol + 0][arow] = rb.x;
        Bs[buf][acol + 1][arow] = rb.y;
        Bs[buf][acol + 2][arow] = rb.z;
        Bs[buf][acol + 3][arow] = rb.w;
    };

    load_tile(0);
    store_tile(0);
    __syncthreads();

    for (int kt = 0; kt < 32; ++kt) {
        const int buf = kt & 1;
        if (kt < 31) load_tile(kt + 1);

#pragma unroll
        for (int k = 0; k < 16; ++k) {
            float a[4], b[4];
            *(float4*)a = *(const float4*)&As[buf][k][ty * 4];
            *(float4*)b = *(const float4*)&Bs[buf][k][tx * 4];
#pragma unroll
            for (int i = 0; i < 4; ++i)
#pragma unroll
                for (int j = 0; j < 4; ++j)
                    acc[i][j] += a[i] * b[j];
        }

        if (kt < 31) {
            store_tile(buf ^ 1);
            __syncthreads();
        }
    }

    float bv[4];
#pragma unroll
    for (int j = 0; j < 4; ++j) bv[j] = __ldg(bias + tx * 4 + j);

    float vout[4][4];
#pragma unroll
    for (int i = 0; i < 4; ++i)
#pragma unroll
        for (int j = 0; j < 4; ++j) vout[i][j] = acc[i][j] + bv[j];

    __syncthreads();
    float* red = (float*)As;

    float mx[4];
#pragma unroll
    for (int i = 0; i < 4; ++i) {
        float v = fmaxf(fmaxf(vout[i][0], vout[i][1]),
                        fmaxf(vout[i][2], vout[i][3]));
        red[(ty * 4 + i) * 17 + tx] = v;
    }
    __syncthreads();
#pragma unroll
    for (int i = 0; i < 4; ++i) {
        float v = -3.402823466e38f;
        const float* rr = red + (ty * 4 + i) * 17;
#pragma unroll
        for (int t = 0; t < 16; ++t) v = fmaxf(v, rr[t]);
        mx[i] = v;
    }
    __syncthreads();

    float lse[4];
#pragma unroll
    for (int i = 0; i < 4; ++i) {
        float s = __expf(vout[i][0] - mx[i]) + __expf(vout[i][1] - mx[i])
                + __expf(vout[i][2] - mx[i]) + __expf(vout[i][3] - mx[i]);
        red[(ty * 4 + i) * 17 + tx] = s;
    }
    __syncthreads();
#pragma unroll
    for (int i = 0; i < 4; ++i) {
        float s = 0.f;
        const float* rr = red + (ty * 4 + i) * 17;
#pragma unroll
        for (int t = 0; t < 16; ++t) s += rr[t];
        lse[i] = mx[i] + logf(s);
    }

#pragma unroll
    for (int i = 0; i < 4; ++i) {
        int mm = m0 + ty * 4 + i;
        if (mm >= NN2) continue;
        float4 o;
        o.x = vout[i][0] - lse[i];
        o.y = vout[i][1] - lse[i];
        o.z = vout[i][2] - lse[i];
        o.w = vout[i][3] - lse[i];
        *(float4*)(out + (size_t)mm * DOUT + tx * 4) = o;
    }
}

// ---------------------------------------------------------------------------
// launch — only harness-owned pointers are passed to kernels
// ---------------------------------------------------------------------------
extern "C" void kernel_launch(void* const* d_in, const int* in_sizes, int n_in,
                              void* d_out, int out_size) {
    const float* x    = (const float*)d_in[0];
    const int*   src1 = (const int*)d_in[1];
    const int*   dst1 = (const int*)d_in[2];
    const int*   src2 = (const int*)d_in[3];
    const int*   dst2 = (const int*)d_in[4];
    const float* Wl1  = (const float*)d_in[5];
    const float* bl1  = (const float*)d_in[6];
    const float* Wr1  = (const float*)d_in[7];
    const float* Wl2  = (const float*)d_in[8];
    const float* bl2  = (const float*)d_in[9];
    const float* Wr2  = (const float*)d_in[10];
    float* out = (float*)d_out;

    // CSR build (device globals referenced in-kernel only)
    k_zero<<<(NN1 + 255) / 256, 256>>>();
    k_hist<<<(NE1 + 255) / 256, 256>>>(dst1, dst2);
    k_alloc1<<<(NN1 + 255) / 256, 256>>>();
    k_alloc2<<<(NN2 + 255) / 256, 256>>>();
    k_bucket1<<<(NE1 + 255) / 256, 256>>>(src1, dst1);
    k_bucket2<<<(NE2 + 255) / 256, 256>>>(src2, dst2);

    // bf16 staging + layer 1
    k_conv_w<<<32, 256>>>(Wl1, Wr1);
    k_conv_x<<<(NN1 * DIN / 4 + 255) / 256, 256>>>(x);
    k_agg1<<<(NN1 * 32 + 255) / 256, 256>>>(x);
    k_gemm1<<<(NN1 + BM1 - 1) / BM1, 256>>>(bl1);

    // layer 2
    k_agg2<<<(NN2 * 32 + 255) / 256, 256>>>();
    k_gemm2<<<(NN2 + 63) / 64, 256>>>(Wl2, Wr2, bl2, out);
}

// round 15
// speedup vs baseline: 2.2533x; 1.0679x over previous
#include <cuda_runtime.h>
#include <cuda_bf16.h>
#include <cstdint>

// Problem dims (fixed by the dataset)
#define NN0   200000
#define NN1   100000
#define NN2   20000
#define NE1   1600000
#define NE2   320000
#define DIN   128
#define DH    256
#define DOUT  64

// GEMM1 tiling (bf16 tensor core)
#define BM1   64
#define BN1   256
#define BK1   32
#define A_TILE_B  (BM1 * 64)        // 4096 B
#define B_TILE_B  (BN1 * 64)        // 16384 B

// ---------------------------------------------------------------------------
// Scratch (static __device__ globals). Referenced ONLY from device code —
// passing their addresses from host code binds the host shadow symbol
// (the R10/R11 bug; GB300 ATS made it a silent wrong-answer, not a fault).
// ---------------------------------------------------------------------------
__device__ __align__(16) __nv_bfloat16 g_h1b[(size_t)NN1 * DH];   // 51.2 MB
__device__ float g_agg2[(size_t)NN2 * DH];                        // 20.5 MB

// CSR build
__device__ int g_cnt1i[NN1];
__device__ int g_off1[NN1];
__device__ int g_cur1[NN1];
__device__ int g_cnt2i[NN2];
__device__ int g_off2[NN2];
__device__ int g_cur2[NN2];
__device__ int g_tot1;
__device__ int g_tot2;
__device__ int g_eidx1[NE1];                  // 6.4 MB
__device__ int g_eidx2[NE2];                  // 1.28 MB

// bf16 staging (xb covers ALL NN0 rows: agg1 gathers from it; +pad for gemm1)
__device__ __align__(16) __nv_bfloat16 g_agg1b[(size_t)(NN1 + BM1) * DIN];
__device__ __align__(16) __nv_bfloat16 g_xb[(size_t)(NN0 + BM1) * DIN];  // 51.2 MB
__device__ __align__(16) __nv_bfloat16 g_Wl1b[DH * DIN];
__device__ __align__(16) __nv_bfloat16 g_Wr1b[DH * DIN];

// ---------------------------------------------------------------------------
// helpers
// ---------------------------------------------------------------------------
__device__ __forceinline__ void cp_async16(uint32_t smem_dst, const void* gmem_src) {
    asm volatile("cp.async.ca.shared.global [%0], [%1], 16;"
                 :: "r"(smem_dst), "l"(gmem_src) : "memory");
}

__device__ __forceinline__ void ldsm_x4(uint32_t& r0, uint32_t& r1,
                                        uint32_t& r2, uint32_t& r3, uint32_t a) {
    asm volatile("ldmatrix.sync.aligned.m8n8.x4.shared.b16 {%0,%1,%2,%3}, [%4];"
                 : "=r"(r0), "=r"(r1), "=r"(r2), "=r"(r3) : "r"(a));
}

__device__ __forceinline__ void mma_bf16(float* c, const uint32_t* a,
                                         uint32_t b0, uint32_t b1) {
    asm volatile(
        "mma.sync.aligned.m16n8k16.row.col.f32.bf16.bf16.f32 "
        "{%0,%1,%2,%3}, {%4,%5,%6,%7}, {%8,%9}, {%0,%1,%2,%3};"
        : "+f"(c[0]), "+f"(c[1]), "+f"(c[2]), "+f"(c[3])
        : "r"(a[0]), "r"(a[1]), "r"(a[2]), "r"(a[3]), "r"(b0), "r"(b1));
}

// ---------------------------------------------------------------------------
// CSR build: zero -> hist -> warp-atomic alloc -> bucket
// ---------------------------------------------------------------------------
__global__ void k_zero() {
    int i = blockIdx.x * blockDim.x + threadIdx.x;
    if (i < NN1) g_cnt1i[i] = 0;
    if (i < NN2) g_cnt2i[i] = 0;
    if (i == 0) { g_tot1 = 0; g_tot2 = 0; }
}

__global__ void k_hist(const int* __restrict__ dst1, const int* __restrict__ dst2) {
    int e = blockIdx.x * blockDim.x + threadIdx.x;
    if (e < NE1) atomicAdd(&g_cnt1i[__ldg(dst1 + e)], 1);
    if (e < NE2) atomicAdd(&g_cnt2i[__ldg(dst2 + e)], 1);
}

__global__ void k_alloc1() {
    int i = blockIdx.x * blockDim.x + threadIdx.x;
    int lane = threadIdx.x & 31;
    int c = (i < NN1) ? g_cnt1i[i] : 0;
    int s = c;
#pragma unroll
    for (int o = 1; o < 32; o <<= 1) {
        int y = __shfl_up_sync(0xffffffffu, s, o);
        if (lane >= o) s += y;
    }
    int wsum = __shfl_sync(0xffffffffu, s, 31);
    int base = 0;
    if (lane == 31) base = atomicAdd(&g_tot1, wsum);
    base = __shfl_sync(0xffffffffu, base, 31);
    int start = base + s - c;
    if (i < NN1) { g_off1[i] = start; g_cur1[i] = start; }
}

__global__ void k_alloc2() {
    int i = blockIdx.x * blockDim.x + threadIdx.x;
    int lane = threadIdx.x & 31;
    int c = (i < NN2) ? g_cnt2i[i] : 0;
    int s = c;
#pragma unroll
    for (int o = 1; o < 32; o <<= 1) {
        int y = __shfl_up_sync(0xffffffffu, s, o);
        if (lane >= o) s += y;
    }
    int wsum = __shfl_sync(0xffffffffu, s, 31);
    int base = 0;
    if (lane == 31) base = atomicAdd(&g_tot2, wsum);
    base = __shfl_sync(0xffffffffu, base, 31);
    int start = base + s - c;
    if (i < NN2) { g_off2[i] = start; g_cur2[i] = start; }
}

__global__ void k_bucket1(const int* __restrict__ src, const int* __restrict__ dst) {
    int e = blockIdx.x * blockDim.x + threadIdx.x;
    if (e >= NE1) return;
    int p = atomicAdd(&g_cur1[__ldg(dst + e)], 1);
    g_eidx1[p] = __ldg(src + e);
}
__global__ void k_bucket2(const int* __restrict__ src, const int* __restrict__ dst) {
    int e = blockIdx.x * blockDim.x + threadIdx.x;
    if (e >= NE2) return;
    int p = atomicAdd(&g_cur2[__ldg(dst + e)], 1);
    g_eidx2[p] = __ldg(src + e);
}

// ---------------------------------------------------------------------------
// conversions to bf16
// ---------------------------------------------------------------------------
__global__ void k_conv_w(const float* __restrict__ Wl, const float* __restrict__ Wr) {
    int i = blockIdx.x * blockDim.x + threadIdx.x;
    if (i >= (DH * DIN) / 4) return;
    float4 a = __ldg((const float4*)Wl + i);
    float4 b = __ldg((const float4*)Wr + i);
    ((__nv_bfloat162*)g_Wl1b)[i * 2 + 0] = __floats2bfloat162_rn(a.x, a.y);
    ((__nv_bfloat162*)g_Wl1b)[i * 2 + 1] = __floats2bfloat162_rn(a.z, a.w);
    ((__nv_bfloat162*)g_Wr1b)[i * 2 + 0] = __floats2bfloat162_rn(b.x, b.y);
    ((__nv_bfloat162*)g_Wr1b)[i * 2 + 1] = __floats2bfloat162_rn(b.z, b.w);
}

// ALL NN0 rows of x -> bf16 (agg1 gathers from this table; gemm1 reads [0,NN1))
__global__ void k_conv_x(const float* __restrict__ x) {
    int i = blockIdx.x * blockDim.x + threadIdx.x;   // over NN0*DIN/4
    if (i >= (NN0 * DIN) / 4) return;
    float4 v = __ldg((const float4*)x + i);
    ((__nv_bfloat162*)g_xb)[i * 2 + 0] = __floats2bfloat162_rn(v.x, v.y);
    ((__nv_bfloat162*)g_xb)[i * 2 + 1] = __floats2bfloat162_rn(v.z, v.w);
}

// ---------------------------------------------------------------------------
// aggregation 1: warp per dst node, gathers bf16 rows from g_xb (256B/edge),
// fp32 register accumulation, writes bf16 with 1/cnt applied.
// ---------------------------------------------------------------------------
__global__ __launch_bounds__(256) void k_agg1() {
    int d = (blockIdx.x * blockDim.x + threadIdx.x) >> 5;
    int lane = threadIdx.x & 31;
    if (d >= NN1) return;
    const int cnt = g_cnt1i[d];
    const int start = g_off1[d];
    float4 acc = make_float4(0.f, 0.f, 0.f, 0.f);
    int i = 0;
    for (; i + 2 <= cnt; i += 2) {
        int s0 = __ldg(g_eidx1 + start + i);
        int s1 = __ldg(g_eidx1 + start + i + 1);
        uint2 u0 = __ldg((const uint2*)(g_xb + (size_t)s0 * DIN) + lane);
        uint2 u1 = __ldg((const uint2*)(g_xb + (size_t)s1 * DIN) + lane);
        float2 a0 = __bfloat1622float2(*(__nv_bfloat162*)&u0.x);
        float2 a1 = __bfloat1622float2(*(__nv_bfloat162*)&u0.y);
        float2 b0 = __bfloat1622float2(*(__nv_bfloat162*)&u1.x);
        float2 b1 = __bfloat1622float2(*(__nv_bfloat162*)&u1.y);
        acc.x += a0.x + b0.x; acc.y += a0.y + b0.y;
        acc.z += a1.x + b1.x; acc.w += a1.y + b1.y;
    }
    if (i < cnt) {
        int s0 = __ldg(g_eidx1 + start + i);
        uint2 u0 = __ldg((const uint2*)(g_xb + (size_t)s0 * DIN) + lane);
        float2 a0 = __bfloat1622float2(*(__nv_bfloat162*)&u0.x);
        float2 a1 = __bfloat1622float2(*(__nv_bfloat162*)&u0.y);
        acc.x += a0.x; acc.y += a0.y; acc.z += a1.x; acc.w += a1.y;
    }
    const float inv = 1.0f / fmaxf((float)cnt, 1.0f);
    __nv_bfloat162* pa = (__nv_bfloat162*)(g_agg1b + (size_t)d * DIN) + lane * 2;
    pa[0] = __floats2bfloat162_rn(acc.x * inv, acc.y * inv);
    pa[1] = __floats2bfloat162_rn(acc.z * inv, acc.w * inv);
}

// ---------------------------------------------------------------------------
// GEMM1 (bf16 tensor core + ldmatrix + cp.async); epilogue writes bf16 h1.
// ---------------------------------------------------------------------------
__global__ __launch_bounds__(256, 2) void k_gemm1(const float* __restrict__ bias) {
    __shared__ __align__(16) char smem[2 * (A_TILE_B + B_TILE_B)];  // 40 KB
    const uint32_t sbase = (uint32_t)__cvta_generic_to_shared(smem);
    const uint32_t aBase[2] = {sbase, sbase + A_TILE_B};
    const uint32_t bBase[2] = {sbase + 2 * A_TILE_B, sbase + 2 * A_TILE_B + B_TILE_B};

    const int tid  = threadIdx.x;
    const int warp = tid >> 5;
    const int lane = tid & 31;
    const int wm   = (warp & 1) * 32;
    const int wn   = (warp >> 1) * 64;
    const int m0   = blockIdx.x * BM1;

    const int arow = tid & 63;
    const int achk = tid >> 6;
    const uint32_t a_dst_off = arow * 64 + 16 * (achk ^ ((arow >> 1) & 3));
    uint32_t b_dst_off[4];
#pragma unroll
    for (int c = 0; c < 4; ++c)
        b_dst_off[c] = tid * 64 + 16 * (c ^ ((tid >> 1) & 3));

    auto cp_tile = [&](int kt, int buf) {
        const int kk = (kt * BK1) & (DIN - 1);
        const __nv_bfloat16* Asrc = ((kt < 4) ? g_agg1b : g_xb)
                                    + (size_t)(m0 + arow) * DIN + kk + achk * 8;
        cp_async16(aBase[buf] + a_dst_off, Asrc);
        const __nv_bfloat16* W = (kt < 4) ? g_Wl1b : g_Wr1b;
        const __nv_bfloat16* Bsrc = W + (size_t)tid * DIN + kk;
#pragma unroll
        for (int c = 0; c < 4; ++c)
            cp_async16(bBase[buf] + b_dst_off[c], Bsrc + c * 8);
        asm volatile("cp.async.commit_group;" ::: "memory");
    };

    uint32_t aoff[2]; int asel[2];
#pragma unroll
    for (int mt = 0; mt < 2; ++mt) {
        int r = wm + mt * 16 + (lane & 7) + ((lane >> 3) & 1) * 8;
        aoff[mt] = r * 64;
        asel[mt] = (r >> 1) & 3;
    }
    const int a_ck = lane >> 4;
    uint32_t boff[4]; int bsel[4];
#pragma unroll
    for (int ntp = 0; ntp < 4; ++ntp) {
        int n = wn + ntp * 16 + (lane & 7) + ((lane >> 4) & 1) * 8;
        boff[ntp] = n * 64;
        bsel[ntp] = (n >> 1) & 3;
    }
    const int b_ck = (lane >> 3) & 1;

    float acc[2][8][4];
#pragma unroll
    for (int mt = 0; mt < 2; ++mt)
#pragma unroll
        for (int nt = 0; nt < 8; ++nt)
#pragma unroll
            for (int q = 0; q < 4; ++q) acc[mt][nt][q] = 0.f;

    cp_tile(0, 0);
    asm volatile("cp.async.wait_group 0;" ::: "memory");
    __syncthreads();

    for (int kt = 0; kt < 8; ++kt) {
        const int buf = kt & 1;
        if (kt < 7) cp_tile(kt + 1, buf ^ 1);

#pragma unroll
        for (int k16 = 0; k16 < 2; ++k16) {
            uint32_t af[2][4];
#pragma unroll
            for (int mt = 0; mt < 2; ++mt)
                ldsm_x4(af[mt][0], af[mt][1], af[mt][2], af[mt][3],
                        aBase[buf] + aoff[mt]
                        + 16 * ((k16 * 2 + a_ck) ^ asel[mt]));
#pragma unroll
            for (int ntp = 0; ntp < 4; ++ntp) {
                uint32_t b0, b1, b2, b3;
                ldsm_x4(b0, b1, b2, b3,
                        bBase[buf] + boff[ntp]
                        + 16 * ((k16 * 2 + b_ck) ^ bsel[ntp]));
                mma_bf16(acc[0][ntp * 2 + 0], af[0], b0, b1);
                mma_bf16(acc[1][ntp * 2 + 0], af[1], b0, b1);
                mma_bf16(acc[0][ntp * 2 + 1], af[0], b2, b3);
                mma_bf16(acc[1][ntp * 2 + 1], af[1], b2, b3);
            }
        }

        if (kt < 7) {
            asm volatile("cp.async.wait_group 0;" ::: "memory");
            __syncthreads();
        }
    }

    // epilogue: bias + relu -> bf16 h1
    const int l4 = lane >> 2;
    const int la3 = lane & 3;
#pragma unroll
    for (int mt = 0; mt < 2; ++mt) {
        const int r0 = m0 + wm + mt * 16 + l4;
#pragma unroll
        for (int half = 0; half < 2; ++half) {
            const int m = r0 + half * 8;
            if (m >= NN1) continue;
            __nv_bfloat16* rowp = g_h1b + (size_t)m * DH;
#pragma unroll
            for (int nt = 0; nt < 8; ++nt) {
                const int ncol = wn + nt * 8 + 2 * la3;
                float v0 = fmaxf(acc[mt][nt][half * 2 + 0] + __ldg(bias + ncol), 0.f);
                float v1 = fmaxf(acc[mt][nt][half * 2 + 1] + __ldg(bias + ncol + 1), 0.f);
                *(__nv_bfloat162*)(rowp + ncol) = __floats2bfloat162_rn(v0, v1);
            }
        }
    }
}

// ---------------------------------------------------------------------------
// aggregation 2: warp per dst node, gathers bf16 h1 rows (512B/edge),
// fp32 accumulation, writes fp32 agg2 with 1/cnt applied.
// Lane covers elements [lane*8, lane*8+8).
// ---------------------------------------------------------------------------
__global__ __launch_bounds__(256) void k_agg2() {
    int d = (blockIdx.x * blockDim.x + threadIdx.x) >> 5;
    int lane = threadIdx.x & 31;
    if (d >= NN2) return;
    const int cnt = g_cnt2i[d];
    const int start = g_off2[d];
    float4 a0 = make_float4(0.f, 0.f, 0.f, 0.f);
    float4 a1 = a0;
    for (int i = 0; i < cnt; ++i) {
        int s = __ldg(g_eidx2 + start + i);
        uint4 u = __ldg((const uint4*)(g_h1b + (size_t)s * DH) + lane);
        float2 f0 = __bfloat1622float2(*(__nv_bfloat162*)&u.x);
        float2 f1 = __bfloat1622float2(*(__nv_bfloat162*)&u.y);
        float2 f2 = __bfloat1622float2(*(__nv_bfloat162*)&u.z);
        float2 f3 = __bfloat1622float2(*(__nv_bfloat162*)&u.w);
        a0.x += f0.x; a0.y += f0.y; a0.z += f1.x; a0.w += f1.y;
        a1.x += f2.x; a1.y += f2.y; a1.z += f3.x; a1.w += f3.y;
    }
    const float inv = 1.0f / fmaxf((float)cnt, 1.0f);
    a0.x *= inv; a0.y *= inv; a0.z *= inv; a0.w *= inv;
    a1.x *= inv; a1.y *= inv; a1.z *= inv; a1.w *= inv;
    float* base = g_agg2 + (size_t)d * DH + lane * 8;
    *(float4*)(base) = a0;
    *(float4*)(base + 4) = a1;
}

// ---------------------------------------------------------------------------
// GEMM2 + fused log_softmax (fp32 math; h1 read as bf16 and upconverted)
// ---------------------------------------------------------------------------
__global__ __launch_bounds__(256, 4) void k_gemm2(const float* __restrict__ Wl,
                                                  const float* __restrict__ Wr,
                                                  const float* __restrict__ bias,
                                                  float* __restrict__ out) {
    __shared__ float As[2][16][68];
    __shared__ float Bs[2][16][64];

    const int m0 = blockIdx.x * 64;
    const int tid = threadIdx.x;
    const int tx = tid & 15;
    const int ty = tid >> 4;
    const int arow = tid >> 2;
    const int acol = (tid & 3) * 4;

    float acc[4][4];
#pragma unroll
    for (int i = 0; i < 4; ++i)
#pragma unroll
        for (int j = 0; j < 4; ++j) acc[i][j] = 0.f;

    const int m = m0 + arow;
    const bool mok = (m < NN2);

    float4 ra, rb;
    auto load_tile = [&](int kt) {
        const int kbase = kt * 16;
        const bool first = (kbase < DH);
        const int kk = first ? kbase : (kbase - DH);
        float4 v = make_float4(0.f, 0.f, 0.f, 0.f);
        if (mok) {
            if (first) {
                v = *(const float4*)(g_agg2 + (size_t)m * DH + kk + acol);
            } else {
                uint2 u = *(const uint2*)(g_h1b + (size_t)m * DH + kk + acol);
                float2 f0 = __bfloat1622float2(*(__nv_bfloat162*)&u.x);
                float2 f1 = __bfloat1622float2(*(__nv_bfloat162*)&u.y);
                v = make_float4(f0.x, f0.y, f1.x, f1.y);
            }
        }
        ra = v;
        const float* W = first ? Wl : Wr;
        rb = __ldg((const float4*)(W + (size_t)arow * DH + kk + acol));
    };
    auto store_tile = [&](int buf) {
        As[buf][acol + 0][arow] = ra.x;
        As[buf][acol + 1][arow] = ra.y;
        As[buf][acol + 2][arow] = ra.z;
        As[buf][acol + 3][arow] = ra.w;
        Bs[buf][acol + 0][arow] = rb.x;
        Bs[buf][acol + 1][arow] = rb.y;
        Bs[buf][acol + 2][arow] = rb.z;
        Bs[buf][acol + 3][arow] = rb.w;
    };

    load_tile(0);
    store_tile(0);
    __syncthreads();

    for (int kt = 0; kt < 32; ++kt) {
        const int buf = kt & 1;
        if (kt < 31) load_tile(kt + 1);

#pragma unroll
        for (int k = 0; k < 16; ++k) {
            float a[4], b[4];
            *(float4*)a = *(const float4*)&As[buf][k][ty * 4];
            *(float4*)b = *(const float4*)&Bs[buf][k][tx * 4];
#pragma unroll
            for (int i = 0; i < 4; ++i)
#pragma unroll
                for (int j = 0; j < 4; ++j)
                    acc[i][j] += a[i] * b[j];
        }

        if (kt < 31) {
            store_tile(buf ^ 1);
            __syncthreads();
        }
    }

    float bv[4];
#pragma unroll
    for (int j = 0; j < 4; ++j) bv[j] = __ldg(bias + tx * 4 + j);

    float vout[4][4];
#pragma unroll
    for (int i = 0; i < 4; ++i)
#pragma unroll
        for (int j = 0; j < 4; ++j) vout[i][j] = acc[i][j] + bv[j];

    __syncthreads();
    float* red = (float*)As;

    float mx[4];
#pragma unroll
    for (int i = 0; i < 4; ++i) {
        float v = fmaxf(fmaxf(vout[i][0], vout[i][1]),
                        fmaxf(vout[i][2], vout[i][3]));
        red[(ty * 4 + i) * 17 + tx] = v;
    }
    __syncthreads();
#pragma unroll
    for (int i = 0; i < 4; ++i) {
        float v = -3.402823466e38f;
        const float* rr = red + (ty * 4 + i) * 17;
#pragma unroll
        for (int t = 0; t < 16; ++t) v = fmaxf(v, rr[t]);
        mx[i] = v;
    }
    __syncthreads();

    float lse[4];
#pragma unroll
    for (int i = 0; i < 4; ++i) {
        float s = __expf(vout[i][0] - mx[i]) + __expf(vout[i][1] - mx[i])
                + __expf(vout[i][2] - mx[i]) + __expf(vout[i][3] - mx[i]);
        red[(ty * 4 + i) * 17 + tx] = s;
    }
    __syncthreads();
#pragma unroll
    for (int i = 0; i < 4; ++i) {
        float s = 0.f;
        const float* rr = red + (ty * 4 + i) * 17;
#pragma unroll
        for (int t = 0; t < 16; ++t) s += rr[t];
        lse[i] = mx[i] + logf(s);
    }

#pragma unroll
    for (int i = 0; i < 4; ++i) {
        int mm = m0 + ty * 4 + i;
        if (mm >= NN2) continue;
        float4 o;
        o.x = vout[i][0] - lse[i];
        o.y = vout[i][1] - lse[i];
        o.z = vout[i][2] - lse[i];
        o.w = vout[i][3] - lse[i];
        *(float4*)(out + (size_t)mm * DOUT + tx * 4) = o;
    }
}

// ---------------------------------------------------------------------------
// launch — only harness-owned pointers are passed to kernels
// ---------------------------------------------------------------------------
extern "C" void kernel_launch(void* const* d_in, const int* in_sizes, int n_in,
                              void* d_out, int out_size) {
    const float* x    = (const float*)d_in[0];
    const int*   src1 = (const int*)d_in[1];
    const int*   dst1 = (const int*)d_in[2];
    const int*   src2 = (const int*)d_in[3];
    const int*   dst2 = (const int*)d_in[4];
    const float* Wl1  = (const float*)d_in[5];
    const float* bl1  = (const float*)d_in[6];
    const float* Wr1  = (const float*)d_in[7];
    const float* Wl2  = (const float*)d_in[8];
    const float* bl2  = (const float*)d_in[9];
    const float* Wr2  = (const float*)d_in[10];
    float* out = (float*)d_out;

    // CSR build (device globals referenced in-kernel only)
    k_zero<<<(NN1 + 255) / 256, 256>>>();
    k_hist<<<(NE1 + 255) / 256, 256>>>(dst1, dst2);
    k_alloc1<<<(NN1 + 255) / 256, 256>>>();
    k_alloc2<<<(NN2 + 255) / 256, 256>>>();
    k_bucket1<<<(NE1 + 255) / 256, 256>>>(src1, dst1);
    k_bucket2<<<(NE2 + 255) / 256, 256>>>(src2, dst2);

    // bf16 staging + layer 1
    k_conv_w<<<32, 256>>>(Wl1, Wr1);
    k_conv_x<<<(NN0 * DIN / 4 + 255) / 256, 256>>>(x);
    k_agg1<<<(NN1 * 32 + 255) / 256, 256>>>();
    k_gemm1<<<(NN1 + BM1 - 1) / BM1, 256>>>(bl1);

    // layer 2
    k_agg2<<<(NN2 * 32 + 255) / 256, 256>>>();
    k_gemm2<<<(NN2 + 63) / 64, 256>>>(Wl2, Wr2, bl2, out);
}